// round 8
// baseline (speedup 1.0000x reference)
#include <cuda_runtime.h>
#include <cuda_bf16.h>
#include <cstdint>
#include <math.h>

// Problem constants
#define BATCH   2
#define S_LEN   2048
#define D_DIM   2048
#define NH      16
#define HD      128
#define LAT     512
#define ROWS_TOT (BATCH * S_LEN)   // 4096

// ---------------------------------------------------------------------------
// Scratch (__device__ globals; allocation-free rule)
// ---------------------------------------------------------------------------
__device__ float g_Q[ROWS_TOT * D_DIM];   // fp32 Q after proj (pre-rope)
__device__ float g_K[ROWS_TOT * D_DIM];   // fp32 K after proj (pre-rope)

__device__ __nv_bfloat16 g_xhi[ROWS_TOT * D_DIM];
__device__ __nv_bfloat16 g_xlo[ROWS_TOT * D_DIM];
__device__ __nv_bfloat16 g_chi[ROWS_TOT * LAT];
__device__ __nv_bfloat16 g_clo[ROWS_TOT * LAT];
__device__ __nv_bfloat16 g_qhi[ROWS_TOT * D_DIM];
__device__ __nv_bfloat16 g_qlo[ROWS_TOT * D_DIM];
__device__ __nv_bfloat16 g_khi[ROWS_TOT * D_DIM];
__device__ __nv_bfloat16 g_klo[ROWS_TOT * D_DIM];
__device__ __nv_bfloat16 g_vhi[ROWS_TOT * D_DIM];
__device__ __nv_bfloat16 g_vlo[ROWS_TOT * D_DIM];
__device__ __nv_bfloat16 g_ohi[ROWS_TOT * D_DIM];
__device__ __nv_bfloat16 g_olo[ROWS_TOT * D_DIM];

// Transposed-weight pool ([N,K] K-major bf16), hi and lo parts.
#define OFF_WQ  0
#define OFF_WDN 4194304
#define OFF_WKU 5242880
#define OFF_WVU 6291456
#define OFF_WO  7340032
#define WT_TOTAL 11534336
__device__ __nv_bfloat16 g_wthi[WT_TOTAL];
__device__ __nv_bfloat16 g_wtlo[WT_TOTAL];

// ---------------------------------------------------------------------------
// PTX helpers (sm_80+ features only — harness targets plain sm_103)
// ---------------------------------------------------------------------------
__device__ __forceinline__ uint32_t smem_u32(const void* p) {
    uint32_t a;
    asm("{ .reg .u64 t; cvta.to.shared.u64 t, %1; cvt.u32.u64 %0, t; }"
        : "=r"(a) : "l"(p));
    return a;
}
__device__ __forceinline__ void cp16(uint32_t dst, const void* src) {
    asm volatile("cp.async.cg.shared.global [%0], [%1], 16;" :: "r"(dst), "l"(src));
}
#define CP_COMMIT() asm volatile("cp.async.commit_group;" ::: "memory")

__device__ __forceinline__ void ldsm4(uint32_t& r0, uint32_t& r1,
                                      uint32_t& r2, uint32_t& r3, uint32_t a) {
    asm volatile("ldmatrix.sync.aligned.m8n8.x4.shared.b16 {%0,%1,%2,%3}, [%4];"
                 : "=r"(r0), "=r"(r1), "=r"(r2), "=r"(r3) : "r"(a));
}
__device__ __forceinline__ void ldsm4t(uint32_t& r0, uint32_t& r1,
                                       uint32_t& r2, uint32_t& r3, uint32_t a) {
    asm volatile("ldmatrix.sync.aligned.m8n8.x4.trans.shared.b16 {%0,%1,%2,%3}, [%4];"
                 : "=r"(r0), "=r"(r1), "=r"(r2), "=r"(r3) : "r"(a));
}
// Non-volatile: pure register op; lets ptxas interleave MMAs to break
// accumulator RAW chains.
__device__ __forceinline__ void mma16816(float* d, const uint32_t* a,
                                         uint32_t b0, uint32_t b1) {
    asm("mma.sync.aligned.m16n8k16.row.col.f32.bf16.bf16.f32 "
        "{%0,%1,%2,%3}, {%4,%5,%6,%7}, {%8,%9}, {%0,%1,%2,%3};"
        : "+f"(d[0]), "+f"(d[1]), "+f"(d[2]), "+f"(d[3])
        : "r"(a[0]), "r"(a[1]), "r"(a[2]), "r"(a[3]), "r"(b0), "r"(b1));
}
__device__ __forceinline__ uint32_t packbf2(__nv_bfloat16 x, __nv_bfloat16 y) {
    __nv_bfloat162 t(x, y);
    return *(uint32_t*)&t;
}

// ---------------------------------------------------------------------------
// HMMA bf16 hi/lo GEMM: C[M,N] = A[M,K] @ Bt[N,K]^T, fp32 accumulation.
// 128x128x32 CTA tile, 128 threads = 4 warps (2x2 grid of 64x64 warp tiles).
// 2-stage cp.async ring, 80KB smem => 2 CTAs/SM (cross-CTA bubble cover)
// while 64x64 warp tiles cut smem fragment traffic per MMA vs 32x64.
// ---------------------------------------------------------------------------
#define ST_AHI  0
#define ST_ALO  10240
#define ST_BHI  20480
#define ST_BLO  30720
#define STAGE_B 40960
#define GK_SMEM_DYN (2 * STAGE_B)   // 80 KB

__global__ __launch_bounds__(128, 2)
void gemm_hilo_kernel(const __nv_bfloat16* __restrict__ Ahi,
                      const __nv_bfloat16* __restrict__ Alo,
                      const __nv_bfloat16* __restrict__ Bhi,
                      const __nv_bfloat16* __restrict__ Blo,
                      float* __restrict__ Cout,
                      __nv_bfloat16* __restrict__ Chi,
                      __nv_bfloat16* __restrict__ Clo,
                      int M, int N, int K)
{
    extern __shared__ char dsm[];
    const uint32_t sbase = smem_u32(dsm);
    const int tid = threadIdx.x, lane = tid & 31, wid = tid >> 5;
    const int wm = wid & 1, wn = wid >> 1;           // 2 x 2 warp grid
    const int m0 = blockIdx.y * 128, n0 = blockIdx.x * 128;

    const __nv_bfloat16* gAh = Ahi + (size_t)m0 * K;
    const __nv_bfloat16* gAl = Alo + (size_t)m0 * K;
    const __nv_bfloat16* gBh = Bhi + (size_t)n0 * K;
    const __nv_bfloat16* gBl = Blo + (size_t)n0 * K;

    float acc[4][8][4];
#pragma unroll
    for (int mt = 0; mt < 4; mt++)
#pragma unroll
        for (int nt = 0; nt < 8; nt++)
#pragma unroll
            for (int r = 0; r < 4; r++) acc[mt][nt][r] = 0.f;

    const int nk = K >> 5;

    // 128 threads: each loads 4x16B per tile (row = tid, 4 column chunks).
    auto load_stage = [&](int buf, int kc) {
        const uint32_t st = sbase + buf * STAGE_B;
        const size_t koff = (size_t)kc * 32;
        const size_t soff0 = (size_t)tid * K + koff;
        const uint32_t doff0 = tid * 80;
#pragma unroll
        for (int c16 = 0; c16 < 4; c16++) {
            const uint32_t doff = doff0 + c16 * 16;
            const size_t soff = soff0 + c16 * 8;
            cp16(st + ST_AHI + doff, gAh + soff);
            cp16(st + ST_ALO + doff, gAl + soff);
            cp16(st + ST_BHI + doff, gBh + soff);
            cp16(st + ST_BLO + doff, gBl + soff);
        }
        CP_COMMIT();
    };

    load_stage(0, 0);

    for (int k = 0; k < nk; k++) {
        asm volatile("cp.async.wait_group 0;" ::: "memory");
        __syncthreads();

        if (k + 1 < nk) load_stage((k + 1) & 1, k + 1);

        const uint32_t st = sbase + (k & 1) * STAGE_B;
#pragma unroll
        for (int ks = 0; ks < 2; ks++) {
            uint32_t ah[4][4], al[4][4];
#pragma unroll
            for (int mt = 0; mt < 4; mt++) {
                const int row = wm * 64 + mt * 16 + (lane & 15);
                const uint32_t off = row * 80 + ks * 32 + ((lane >> 4) << 4);
                ldsm4(ah[mt][0], ah[mt][1], ah[mt][2], ah[mt][3],
                      st + ST_AHI + off);
                ldsm4(al[mt][0], al[mt][1], al[mt][2], al[mt][3],
                      st + ST_ALO + off);
            }
#pragma unroll
            for (int bp = 0; bp < 4; bp++) {
                const int rn = wn * 64 + bp * 16 + ((lane >> 4) << 3) + (lane & 7);
                const uint32_t off = rn * 80 + ks * 32 + (((lane >> 3) & 1) << 4);
                uint32_t bh[4], bl[4];
                ldsm4(bh[0], bh[1], bh[2], bh[3], st + ST_BHI + off);
                ldsm4(bl[0], bl[1], bl[2], bl[3], st + ST_BLO + off);
                // term-major: 8 independent accumulators between reuse
#pragma unroll
                for (int mt = 0; mt < 4; mt++)
#pragma unroll
                    for (int h = 0; h < 2; h++)
                        mma16816(acc[mt][2 * bp + h], ah[mt], bh[2 * h], bh[2 * h + 1]);
#pragma unroll
                for (int mt = 0; mt < 4; mt++)
#pragma unroll
                    for (int h = 0; h < 2; h++)
                        mma16816(acc[mt][2 * bp + h], ah[mt], bl[2 * h], bl[2 * h + 1]);
#pragma unroll
                for (int mt = 0; mt < 4; mt++)
#pragma unroll
                    for (int h = 0; h < 2; h++)
                        mma16816(acc[mt][2 * bp + h], al[mt], bh[2 * h], bh[2 * h + 1]);
            }
        }
    }

    const int lr = lane >> 2, lc = (lane & 3) * 2;
    const int rbase = m0 + wm * 64, cbase = n0 + wn * 64;
    if (Cout) {
#pragma unroll
        for (int mt = 0; mt < 4; mt++) {
#pragma unroll
            for (int nt = 0; nt < 8; nt++) {
                float* d = acc[mt][nt];
                const size_t r0 = (size_t)(rbase + mt * 16 + lr) * N
                                  + cbase + nt * 8 + lc;
                *(float2*)(Cout + r0)         = make_float2(d[0], d[1]);
                *(float2*)(Cout + r0 + 8 * N) = make_float2(d[2], d[3]);
            }
        }
    } else {
#pragma unroll
        for (int mt = 0; mt < 4; mt++) {
#pragma unroll
            for (int nt = 0; nt < 8; nt++) {
                float* d = acc[mt][nt];
#pragma unroll
                for (int half = 0; half < 2; half++) {
                    float v0 = d[half * 2], v1 = d[half * 2 + 1];
                    __nv_bfloat16 h0 = __float2bfloat16(v0);
                    __nv_bfloat16 h1 = __float2bfloat16(v1);
                    __nv_bfloat16 l0 = __float2bfloat16(v0 - __bfloat162float(h0));
                    __nv_bfloat16 l1 = __float2bfloat16(v1 - __bfloat162float(h1));
                    const size_t o = (size_t)(rbase + mt * 16 + lr + half * 8) * N
                                     + cbase + nt * 8 + lc;
                    *(__nv_bfloat162*)(Chi + o) = __nv_bfloat162(h0, h1);
                    *(__nv_bfloat162*)(Clo + o) = __nv_bfloat162(l0, l1);
                }
            }
        }
    }
}

// ---------------------------------------------------------------------------
// fp32 -> bf16 hi/lo elementwise (for x)
// ---------------------------------------------------------------------------
__global__ void convert_hilo_kernel(const float* __restrict__ in,
                                    __nv_bfloat16* __restrict__ hi,
                                    __nv_bfloat16* __restrict__ lo, int n)
{
    int i = blockIdx.x * blockDim.x + threadIdx.x;
    if (i >= n) return;
    float v = in[i];
    __nv_bfloat16 h = __float2bfloat16(v);
    hi[i] = h;
    lo[i] = __float2bfloat16(v - __bfloat162float(h));
}

// ---------------------------------------------------------------------------
// W [Kd,Nd] fp32 -> Wt hi/lo [Nd,Kd] bf16 (tiled transpose)
// ---------------------------------------------------------------------------
__global__ void transpose_hilo_kernel(const float* __restrict__ W,
                                      __nv_bfloat16* __restrict__ hi,
                                      __nv_bfloat16* __restrict__ lo,
                                      int Kd, int Nd)
{
    __shared__ float t[32][33];
    const int tx = threadIdx.x, ty = threadIdx.y;
    const int k0 = blockIdx.y * 32, n0 = blockIdx.x * 32;
#pragma unroll
    for (int i = 0; i < 4; i++)
        t[ty + i * 8][tx] = W[(size_t)(k0 + ty + i * 8) * Nd + n0 + tx];
    __syncthreads();
#pragma unroll
    for (int i = 0; i < 4; i++) {
        float v = t[tx][ty + i * 8];
        __nv_bfloat16 h = __float2bfloat16(v);
        size_t o = (size_t)(n0 + ty + i * 8) * Kd + k0 + tx;
        hi[o] = h;
        lo[o] = __float2bfloat16(v - __bfloat162float(h));
    }
}

// ---------------------------------------------------------------------------
// RoPE on fp32 Q,K -> bf16 hi/lo outputs (fused rope + split)
// ---------------------------------------------------------------------------
__global__ void rope_convert_kernel(const float* __restrict__ Q,
                                    const float* __restrict__ K,
                                    const float* __restrict__ freqs,
                                    __nv_bfloat16* __restrict__ qhi,
                                    __nv_bfloat16* __restrict__ qlo,
                                    __nv_bfloat16* __restrict__ khi,
                                    __nv_bfloat16* __restrict__ klo)
{
    const int total = BATCH * S_LEN * NH * (HD / 2);
    int idx = blockIdx.x * blockDim.x + threadIdx.x;
    if (idx >= total) return;
    int p = idx & 63;
    int s = (idx >> 10) & (S_LEN - 1);
    float f = freqs[s * (HD / 2) + p];
    float sn, cs;
    sincosf(f, &sn, &cs);

    const float2 q = ((const float2*)Q)[idx];
    const float2 k = ((const float2*)K)[idx];
    float q0 = q.x * cs - q.y * sn, q1 = q.x * sn + q.y * cs;
    float k0 = k.x * cs - k.y * sn, k1 = k.x * sn + k.y * cs;

    __nv_bfloat16 qh0 = __float2bfloat16(q0), qh1 = __float2bfloat16(q1);
    __nv_bfloat16 kh0 = __float2bfloat16(k0), kh1 = __float2bfloat16(k1);
    ((__nv_bfloat162*)qhi)[idx] = __nv_bfloat162(qh0, qh1);
    ((__nv_bfloat162*)qlo)[idx] = __nv_bfloat162(
        __float2bfloat16(q0 - __bfloat162float(qh0)),
        __float2bfloat16(q1 - __bfloat162float(qh1)));
    ((__nv_bfloat162*)khi)[idx] = __nv_bfloat162(kh0, kh1);
    ((__nv_bfloat162*)klo)[idx] = __nv_bfloat162(
        __float2bfloat16(k0 - __bfloat162float(kh0)),
        __float2bfloat16(k1 - __bfloat162float(kh1)));
}

// ---------------------------------------------------------------------------
// HMMA causal flash attention, bf16 hi/lo (3-term QK and PV), fp32 softmax.
// BR=BC=64, 128 threads (4 warps x 16 q-rows). Single-buffered K/V smem
// (104KB => 2 CTAs/SM). MMAs term-major. Unchanged from round 6.
// ---------------------------------------------------------------------------
#define FP   136
#define FPB  272
#define FT   17408
#define SQHI 0
#define SQLO 17408
#define SKHI 34816
#define SKLO 52224
#define SVHI 69632
#define SVLO 87040
#define FL_SMEM 104448

__global__ __launch_bounds__(128)
void flash_hmma_kernel(const __nv_bfloat16* __restrict__ Qhi,
                       const __nv_bfloat16* __restrict__ Qlo,
                       const __nv_bfloat16* __restrict__ Khi,
                       const __nv_bfloat16* __restrict__ Klo,
                       const __nv_bfloat16* __restrict__ Vhi,
                       const __nv_bfloat16* __restrict__ Vlo,
                       __nv_bfloat16* __restrict__ Ohi,
                       __nv_bfloat16* __restrict__ Olo)
{
    extern __shared__ char dsm[];
    const uint32_t sb = smem_u32(dsm);

    const int tid = threadIdx.x, lane = tid & 31, wm = tid >> 5;
    const int lr = lane >> 2, lc2 = (lane & 3) * 2;

    const int bh_ = blockIdx.y;
    const int b = bh_ >> 4, head = bh_ & 15;
    const int qi = gridDim.x - 1 - blockIdx.x;       // heavy blocks first
    const int q0 = qi * 64;
    const size_t base = ((size_t)b * S_LEN) * D_DIM + head * HD;

#pragma unroll
    for (int j = 0; j < 8; j++) {
        int lin = j * 128 + tid;
        int row = lin >> 4, c16 = lin & 15;
        const size_t so = base + (size_t)(q0 + row) * D_DIM + c16 * 8;
        const uint32_t doff = row * FPB + c16 * 16;
        cp16(sb + SQHI + doff, Qhi + so);
        cp16(sb + SQLO + doff, Qlo + so);
    }
    CP_COMMIT();

    float m[2] = {-1e30f, -1e30f}, l[2] = {0.f, 0.f};
    float accO[16][4];
#pragma unroll
    for (int nt = 0; nt < 16; nt++)
#pragma unroll
        for (int e = 0; e < 4; e++) accO[nt][e] = 0.f;

    const float scale = 0.08838834764831845f;
    const int qrow_base = q0 + wm * 16;

    for (int kt = 0; kt <= qi; kt++) {
        const int k0g = kt * 64;
        __syncthreads();
#pragma unroll
        for (int j = 0; j < 8; j++) {
            int lin = j * 128 + tid;
            int row = lin >> 4, c16 = lin & 15;
            const size_t so = base + (size_t)(k0g + row) * D_DIM + c16 * 8;
            const uint32_t doff = row * FPB + c16 * 16;
            cp16(sb + SKHI + doff, Khi + so);
            cp16(sb + SKLO + doff, Klo + so);
            cp16(sb + SVHI + doff, Vhi + so);
            cp16(sb + SVLO + doff, Vlo + so);
        }
        CP_COMMIT();
        asm volatile("cp.async.wait_group 0;" ::: "memory");
        __syncthreads();

        float accS[8][4];
#pragma unroll
        for (int n = 0; n < 8; n++)
#pragma unroll
            for (int e = 0; e < 4; e++) accS[n][e] = 0.f;

#pragma unroll
        for (int ks = 0; ks < 8; ks++) {
            const int kk = ks * 16;
            uint32_t qh[4], ql[4];
            const uint32_t qoff = (wm * 16 + (lane & 15)) * FPB
                                  + (kk + ((lane >> 4) << 3)) * 2;
            ldsm4(qh[0], qh[1], qh[2], qh[3], sb + SQHI + qoff);
            ldsm4(ql[0], ql[1], ql[2], ql[3], sb + SQLO + qoff);
#pragma unroll
            for (int np = 0; np < 4; np++) {
                const uint32_t koff =
                    (np * 16 + (lane & 7) + ((lane >> 4) << 3)) * FPB
                    + (kk + (((lane >> 3) & 1) << 3)) * 2;
                uint32_t bh[4], bl[4];
                ldsm4(bh[0], bh[1], bh[2], bh[3], sb + SKHI + koff);
                ldsm4(bl[0], bl[1], bl[2], bl[3], sb + SKLO + koff);
#pragma unroll
                for (int t = 0; t < 2; t++)
                    mma16816(accS[np * 2 + t], qh, bh[2 * t], bh[2 * t + 1]);
#pragma unroll
                for (int t = 0; t < 2; t++)
                    mma16816(accS[np * 2 + t], qh, bl[2 * t], bl[2 * t + 1]);
#pragma unroll
                for (int t = 0; t < 2; t++)
                    mma16816(accS[np * 2 + t], ql, bh[2 * t], bh[2 * t + 1]);
            }
        }

        const bool diag = (kt == qi);
#pragma unroll
        for (int n = 0; n < 8; n++) {
#pragma unroll
            for (int e = 0; e < 4; e++) {
                float v = accS[n][e] * scale;
                if (diag) {
                    int row = qrow_base + lr + 8 * (e >> 1);
                    int col = k0g + n * 8 + lc2 + (e & 1);
                    if (col > row) v = -1e30f;
                }
                accS[n][e] = v;
            }
        }

#pragma unroll
        for (int h = 0; h < 2; h++) {
            float mt = -1e30f;
#pragma unroll
            for (int n = 0; n < 8; n++)
                mt = fmaxf(mt, fmaxf(accS[n][2 * h], accS[n][2 * h + 1]));
            mt = fmaxf(mt, __shfl_xor_sync(0xffffffffu, mt, 1));
            mt = fmaxf(mt, __shfl_xor_sync(0xffffffffu, mt, 2));
            float mn = fmaxf(m[h], mt);
            float alpha = __expf(m[h] - mn);
            m[h] = mn;
            float lt = 0.f;
#pragma unroll
            for (int n = 0; n < 8; n++) {
                float p0 = __expf(accS[n][2 * h] - mn);
                float p1 = __expf(accS[n][2 * h + 1] - mn);
                accS[n][2 * h] = p0;
                accS[n][2 * h + 1] = p1;
                lt += p0 + p1;
            }
            lt += __shfl_xor_sync(0xffffffffu, lt, 1);
            lt += __shfl_xor_sync(0xffffffffu, lt, 2);
            l[h] = l[h] * alpha + lt;
#pragma unroll
            for (int nt = 0; nt < 16; nt++) {
                accO[nt][2 * h] *= alpha;
                accO[nt][2 * h + 1] *= alpha;
            }
        }

#pragma unroll
        for (int t = 0; t < 4; t++) {
            uint32_t phi[4], plo[4];
#pragma unroll
            for (int half = 0; half < 2; half++) {
                float* s = accS[2 * t + half];
#pragma unroll
                for (int rh = 0; rh < 2; rh++) {
                    float v0 = s[2 * rh], v1 = s[2 * rh + 1];
                    __nv_bfloat16 h0 = __float2bfloat16(v0);
                    __nv_bfloat16 h1 = __float2bfloat16(v1);
                    phi[half * 2 + rh] = packbf2(h0, h1);
                    plo[half * 2 + rh] = packbf2(
                        __float2bfloat16(v0 - __bfloat162float(h0)),
                        __float2bfloat16(v1 - __bfloat162float(h1)));
                }
            }
            const int kk = t * 16;
#pragma unroll
            for (int np = 0; np < 8; np++) {
                const uint32_t voff = (kk + (lane & 15)) * FPB
                                      + (np * 16 + ((lane >> 4) << 3)) * 2;
                uint32_t vh[4], vl[4];
                ldsm4t(vh[0], vh[1], vh[2], vh[3], sb + SVHI + voff);
                ldsm4t(vl[0], vl[1], vl[2], vl[3], sb + SVLO + voff);
#pragma unroll
                for (int u = 0; u < 2; u++)
                    mma16816(accO[np * 2 + u], phi, vh[2 * u], vh[2 * u + 1]);
#pragma unroll
                for (int u = 0; u < 2; u++)
                    mma16816(accO[np * 2 + u], phi, vl[2 * u], vl[2 * u + 1]);
#pragma unroll
                for (int u = 0; u < 2; u++)
                    mma16816(accO[np * 2 + u], plo, vh[2 * u], vh[2 * u + 1]);
            }
        }
    }

    const float inv0 = 1.0f / l[0], inv1 = 1.0f / l[1];
#pragma unroll
    for (int nt = 0; nt < 16; nt++) {
#pragma unroll
        for (int h = 0; h < 2; h++) {
            float inv = h ? inv1 : inv0;
            float v0 = accO[nt][2 * h] * inv;
            float v1 = accO[nt][2 * h + 1] * inv;
            __nv_bfloat16 h0 = __float2bfloat16(v0);
            __nv_bfloat16 h1 = __float2bfloat16(v1);
            const size_t o = base
                + (size_t)(qrow_base + lr + 8 * h) * D_DIM + nt * 8 + lc2;
            *(uint32_t*)(Ohi + o) = packbf2(h0, h1);
            *(uint32_t*)(Olo + o) = packbf2(
                __float2bfloat16(v0 - __bfloat162float(h0)),
                __float2bfloat16(v1 - __bfloat162float(h1)));
        }
    }
}

// ---------------------------------------------------------------------------
// Launch
// Inputs: x, freqs, mask(unused: exactly causal), Wq, Wdown, Wkup, Wvup, Wo
// ---------------------------------------------------------------------------
extern "C" void kernel_launch(void* const* d_in, const int* in_sizes, int n_in,
                              void* d_out, int out_size)
{
    const float* x     = (const float*)d_in[0];
    const float* freqs = (const float*)d_in[1];
    const float* Wq    = (const float*)d_in[3];
    const float* Wdn   = (const float*)d_in[4];
    const float* Wku   = (const float*)d_in[5];
    const float* Wvu   = (const float*)d_in[6];
    const float* Wo    = (const float*)d_in[7];
    float* out = (float*)d_out;

    float *Qb, *Kb;
    __nv_bfloat16 *xhi, *xlo, *chi, *clo, *wthi, *wtlo;
    __nv_bfloat16 *qhi, *qlo, *khi, *klo, *vhi, *vlo, *ohi, *olo;
    cudaGetSymbolAddress((void**)&Qb, g_Q);
    cudaGetSymbolAddress((void**)&Kb, g_K);
    cudaGetSymbolAddress((void**)&xhi, g_xhi);
    cudaGetSymbolAddress((void**)&xlo, g_xlo);
    cudaGetSymbolAddress((void**)&chi, g_chi);
    cudaGetSymbolAddress((void**)&clo, g_clo);
    cudaGetSymbolAddress((void**)&qhi, g_qhi);
    cudaGetSymbolAddress((void**)&qlo, g_qlo);
    cudaGetSymbolAddress((void**)&khi, g_khi);
    cudaGetSymbolAddress((void**)&klo, g_klo);
    cudaGetSymbolAddress((void**)&vhi, g_vhi);
    cudaGetSymbolAddress((void**)&vlo, g_vlo);
    cudaGetSymbolAddress((void**)&ohi, g_ohi);
    cudaGetSymbolAddress((void**)&olo, g_olo);
    cudaGetSymbolAddress((void**)&wthi, g_wthi);
    cudaGetSymbolAddress((void**)&wtlo, g_wtlo);

    cudaFuncSetAttribute(gemm_hilo_kernel,
                         cudaFuncAttributeMaxDynamicSharedMemorySize, GK_SMEM_DYN);
    cudaFuncSetAttribute(flash_hmma_kernel,
                         cudaFuncAttributeMaxDynamicSharedMemorySize, FL_SMEM);

    // Weight transposes + x conversion (bandwidth-bound)
    dim3 tb(32, 8);
    transpose_hilo_kernel<<<dim3(64, 64), tb>>>(Wq,  wthi + OFF_WQ,  wtlo + OFF_WQ,  2048, 2048);
    transpose_hilo_kernel<<<dim3(16, 64), tb>>>(Wdn, wthi + OFF_WDN, wtlo + OFF_WDN, 2048, 512);
    transpose_hilo_kernel<<<dim3(64, 16), tb>>>(Wku, wthi + OFF_WKU, wtlo + OFF_WKU, 512, 2048);
    transpose_hilo_kernel<<<dim3(64, 16), tb>>>(Wvu, wthi + OFF_WVU, wtlo + OFF_WVU, 512, 2048);
    transpose_hilo_kernel<<<dim3(64, 64), tb>>>(Wo,  wthi + OFF_WO,  wtlo + OFF_WO,  2048, 2048);

    const int nx = ROWS_TOT * D_DIM;
    convert_hilo_kernel<<<nx / 256, 256>>>(x, xhi, xlo, nx);

    // Projections (HMMA bf16 hi/lo, fp32 accum). 128x128 tiles, 128 thr.
    gemm_hilo_kernel<<<dim3(16, 32), 128, GK_SMEM_DYN>>>(
        xhi, xlo, wthi + OFF_WQ, wtlo + OFF_WQ, Qb, nullptr, nullptr,
        ROWS_TOT, D_DIM, D_DIM);
    gemm_hilo_kernel<<<dim3(4, 32), 128, GK_SMEM_DYN>>>(
        xhi, xlo, wthi + OFF_WDN, wtlo + OFF_WDN, nullptr, chi, clo,
        ROWS_TOT, LAT, D_DIM);
    gemm_hilo_kernel<<<dim3(16, 32), 128, GK_SMEM_DYN>>>(
        chi, clo, wthi + OFF_WKU, wtlo + OFF_WKU, Kb, nullptr, nullptr,
        ROWS_TOT, D_DIM, LAT);
    gemm_hilo_kernel<<<dim3(16, 32), 128, GK_SMEM_DYN>>>(
        chi, clo, wthi + OFF_WVU, wtlo + OFF_WVU, nullptr, vhi, vlo,
        ROWS_TOT, D_DIM, LAT);

    // RoPE + bf16 hi/lo split for Q,K
    const int pairs = BATCH * S_LEN * NH * (HD / 2);
    rope_convert_kernel<<<(pairs + 255) / 256, 256>>>(
        Qb, Kb, freqs, qhi, qlo, khi, klo);

    // Flash attention (causal, HMMA hi/lo) -> O as bf16 hi/lo
    flash_hmma_kernel<<<dim3(S_LEN / 64, BATCH * NH), 128, FL_SMEM>>>(
        qhi, qlo, khi, klo, vhi, vlo, ohi, olo);

    // Output projection
    gemm_hilo_kernel<<<dim3(16, 32), 128, GK_SMEM_DYN>>>(
        ohi, olo, wthi + OFF_WO, wtlo + OFF_WO, out, nullptr, nullptr,
        ROWS_TOT, D_DIM, D_DIM);
}

// round 9
// speedup vs baseline: 1.1852x; 1.1852x over previous
#include <cuda_runtime.h>
#include <cuda_bf16.h>
#include <cstdint>
#include <math.h>

// Problem constants
#define BATCH   2
#define S_LEN   2048
#define D_DIM   2048
#define NH      16
#define HD      128
#define LAT     512
#define ROWS_TOT (BATCH * S_LEN)   // 4096
#define KV_W    4096               // merged K|V row width

// ---------------------------------------------------------------------------
// Scratch (__device__ globals; allocation-free rule)
// ---------------------------------------------------------------------------
__device__ __nv_bfloat16 g_xhi[ROWS_TOT * D_DIM];
__device__ __nv_bfloat16 g_xlo[ROWS_TOT * D_DIM];
__device__ __nv_bfloat16 g_chi[ROWS_TOT * LAT];
__device__ __nv_bfloat16 g_clo[ROWS_TOT * LAT];
__device__ __nv_bfloat16 g_qhi[ROWS_TOT * D_DIM];
__device__ __nv_bfloat16 g_qlo[ROWS_TOT * D_DIM];
__device__ __nv_bfloat16 g_kvhi[ROWS_TOT * KV_W];   // cols [0,2048)=K(roped), [2048,4096)=V
__device__ __nv_bfloat16 g_kvlo[ROWS_TOT * KV_W];
__device__ __nv_bfloat16 g_ohi[ROWS_TOT * D_DIM];
__device__ __nv_bfloat16 g_olo[ROWS_TOT * D_DIM];

// Transposed-weight pool ([N,K] K-major bf16), hi and lo parts.
// NOTE: WKU and WVU are contiguous -> single merged KV GEMM (N=4096, K=512).
#define OFF_WQ  0
#define OFF_WDN 4194304
#define OFF_WKU 5242880
#define OFF_WVU 6291456
#define OFF_WO  7340032
#define WT_TOTAL 11534336
__device__ __nv_bfloat16 g_wthi[WT_TOTAL];
__device__ __nv_bfloat16 g_wtlo[WT_TOTAL];

// ---------------------------------------------------------------------------
// PTX helpers (sm_80+ features only — harness targets plain sm_103)
// ---------------------------------------------------------------------------
__device__ __forceinline__ uint32_t smem_u32(const void* p) {
    uint32_t a;
    asm("{ .reg .u64 t; cvta.to.shared.u64 t, %1; cvt.u32.u64 %0, t; }"
        : "=r"(a) : "l"(p));
    return a;
}
__device__ __forceinline__ void cp16(uint32_t dst, const void* src) {
    asm volatile("cp.async.cg.shared.global [%0], [%1], 16;" :: "r"(dst), "l"(src));
}
#define CP_COMMIT() asm volatile("cp.async.commit_group;" ::: "memory")

__device__ __forceinline__ void ldsm4(uint32_t& r0, uint32_t& r1,
                                      uint32_t& r2, uint32_t& r3, uint32_t a) {
    asm volatile("ldmatrix.sync.aligned.m8n8.x4.shared.b16 {%0,%1,%2,%3}, [%4];"
                 : "=r"(r0), "=r"(r1), "=r"(r2), "=r"(r3) : "r"(a));
}
__device__ __forceinline__ void ldsm4t(uint32_t& r0, uint32_t& r1,
                                       uint32_t& r2, uint32_t& r3, uint32_t a) {
    asm volatile("ldmatrix.sync.aligned.m8n8.x4.trans.shared.b16 {%0,%1,%2,%3}, [%4];"
                 : "=r"(r0), "=r"(r1), "=r"(r2), "=r"(r3) : "r"(a));
}
// Non-volatile: pure register op; lets ptxas interleave MMAs to break
// accumulator RAW chains.
__device__ __forceinline__ void mma16816(float* d, const uint32_t* a,
                                         uint32_t b0, uint32_t b1) {
    asm("mma.sync.aligned.m16n8k16.row.col.f32.bf16.bf16.f32 "
        "{%0,%1,%2,%3}, {%4,%5,%6,%7}, {%8,%9}, {%0,%1,%2,%3};"
        : "+f"(d[0]), "+f"(d[1]), "+f"(d[2]), "+f"(d[3])
        : "r"(a[0]), "r"(a[1]), "r"(a[2]), "r"(a[3]), "r"(b0), "r"(b1));
}
__device__ __forceinline__ uint32_t packbf2(__nv_bfloat16 x, __nv_bfloat16 y) {
    __nv_bfloat162 t(x, y);
    return *(uint32_t*)&t;
}

// ---------------------------------------------------------------------------
// HMMA bf16 hi/lo GEMM (persistent): C[M,N] = A[M,K] @ Bt[N,K]^T, fp32 acc.
// Round-6 mainloop: 128x128x32 CTA tile, 256 thr (8 warps, 4x2 of 32x64),
// 2-stage cp.async ring (80KB smem => 2 CTAs/SM), term-major MMA order.
// Persistent tile loop kills wave quantization. Epilogues:
//   Cout != null           : fp32 store
//   else                   : bf16 hi/lo store; columns < rope_cols get RoPE
//                            (freqs != null) applied in fp32 first.
// ---------------------------------------------------------------------------
#define ST_AHI  0
#define ST_ALO  10240
#define ST_BHI  20480
#define ST_BLO  30720
#define STAGE_B 40960
#define GK_SMEM_DYN (2 * STAGE_B)   // 80 KB
#define GK_GRID 296                 // 2 CTAs x 148 SMs

__global__ __launch_bounds__(256, 2)
void gemm_hilo_kernel(const __nv_bfloat16* __restrict__ Ahi,
                      const __nv_bfloat16* __restrict__ Alo,
                      const __nv_bfloat16* __restrict__ Bhi,
                      const __nv_bfloat16* __restrict__ Blo,
                      float* __restrict__ Cout,
                      __nv_bfloat16* __restrict__ Chi,
                      __nv_bfloat16* __restrict__ Clo,
                      const float* __restrict__ freqs,
                      int rope_cols,
                      int M, int N, int K)
{
    extern __shared__ char dsm[];
    const uint32_t sbase = smem_u32(dsm);
    const int tid = threadIdx.x, lane = tid & 31, wid = tid >> 5;
    const int wm = wid & 3, wn = wid >> 2;           // 4 x 2 warp grid
    const int lrow = tid >> 1;
    const int lc0  = (tid & 1) * 2;
    const int lr = lane >> 2, lc = (lane & 3) * 2;
    const int nk = K >> 5;
    const int ntx = N >> 7;
    const int ntiles = (M >> 7) * ntx;

    for (int tile = blockIdx.x; tile < ntiles; tile += gridDim.x) {
        const int tyi = tile / ntx;
        const int txi = tile - tyi * ntx;
        const int m0 = tyi * 128, n0 = txi * 128;

        const __nv_bfloat16* gAh = Ahi + (size_t)m0 * K;
        const __nv_bfloat16* gAl = Alo + (size_t)m0 * K;
        const __nv_bfloat16* gBh = Bhi + (size_t)n0 * K;
        const __nv_bfloat16* gBl = Blo + (size_t)n0 * K;

        float acc[2][8][4];
#pragma unroll
        for (int mt = 0; mt < 2; mt++)
#pragma unroll
            for (int nt = 0; nt < 8; nt++)
#pragma unroll
                for (int r = 0; r < 4; r++) acc[mt][nt][r] = 0.f;

        auto load_stage = [&](int buf, int kc) {
            const uint32_t st = sbase + buf * STAGE_B;
            const size_t koff = (size_t)kc * 32;
#pragma unroll
            for (int t = 0; t < 2; t++) {
                const int c16 = lc0 + t;
                const uint32_t doff = lrow * 80 + c16 * 16;
                const size_t soff = (size_t)lrow * K + koff + c16 * 8;
                cp16(st + ST_AHI + doff, gAh + soff);
                cp16(st + ST_ALO + doff, gAl + soff);
                cp16(st + ST_BHI + doff, gBh + soff);
                cp16(st + ST_BLO + doff, gBl + soff);
            }
            CP_COMMIT();
        };

        load_stage(0, 0);

        for (int k = 0; k < nk; k++) {
            asm volatile("cp.async.wait_group 0;" ::: "memory");
            __syncthreads();

            if (k + 1 < nk) load_stage((k + 1) & 1, k + 1);

            const uint32_t st = sbase + (k & 1) * STAGE_B;
#pragma unroll
            for (int ks = 0; ks < 2; ks++) {
                uint32_t ah[2][4], al[2][4];
#pragma unroll
                for (int mt = 0; mt < 2; mt++) {
                    const int row = wm * 32 + mt * 16 + (lane & 15);
                    const uint32_t off = row * 80 + ks * 32 + ((lane >> 4) << 4);
                    ldsm4(ah[mt][0], ah[mt][1], ah[mt][2], ah[mt][3],
                          st + ST_AHI + off);
                    ldsm4(al[mt][0], al[mt][1], al[mt][2], al[mt][3],
                          st + ST_ALO + off);
                }
#pragma unroll
                for (int bp = 0; bp < 4; bp++) {
                    const int rn = wn * 64 + bp * 16 + ((lane >> 4) << 3) + (lane & 7);
                    const uint32_t off = rn * 80 + ks * 32 + (((lane >> 3) & 1) << 4);
                    uint32_t bh[4], bl[4];
                    ldsm4(bh[0], bh[1], bh[2], bh[3], st + ST_BHI + off);
                    ldsm4(bl[0], bl[1], bl[2], bl[3], st + ST_BLO + off);
                    // term-major: 4 independent accumulators between reuse
#pragma unroll
                    for (int mt = 0; mt < 2; mt++)
#pragma unroll
                        for (int h = 0; h < 2; h++)
                            mma16816(acc[mt][2 * bp + h], ah[mt], bh[2 * h], bh[2 * h + 1]);
#pragma unroll
                    for (int mt = 0; mt < 2; mt++)
#pragma unroll
                        for (int h = 0; h < 2; h++)
                            mma16816(acc[mt][2 * bp + h], ah[mt], bl[2 * h], bl[2 * h + 1]);
#pragma unroll
                    for (int mt = 0; mt < 2; mt++)
#pragma unroll
                        for (int h = 0; h < 2; h++)
                            mma16816(acc[mt][2 * bp + h], al[mt], bh[2 * h], bh[2 * h + 1]);
                }
            }
        }

        const int rbase = m0 + wm * 32, cbase = n0 + wn * 64;
        if (Cout) {
#pragma unroll
            for (int mt = 0; mt < 2; mt++) {
#pragma unroll
                for (int nt = 0; nt < 8; nt++) {
                    float* d = acc[mt][nt];
                    const size_t r0 = (size_t)(rbase + mt * 16 + lr) * N
                                      + cbase + nt * 8 + lc;
                    *(float2*)(Cout + r0)         = make_float2(d[0], d[1]);
                    *(float2*)(Cout + r0 + 8 * N) = make_float2(d[2], d[3]);
                }
            }
        } else {
            const bool do_rope = (freqs != nullptr) && (cbase < rope_cols);
#pragma unroll
            for (int mt = 0; mt < 2; mt++) {
#pragma unroll
                for (int nt = 0; nt < 8; nt++) {
                    float* d = acc[mt][nt];
#pragma unroll
                    for (int half = 0; half < 2; half++) {
                        const int row = rbase + mt * 16 + lr + half * 8;
                        const int col = cbase + nt * 8 + lc;
                        float v0 = d[half * 2], v1 = d[half * 2 + 1];
                        if (do_rope) {
                            const int s = row & (S_LEN - 1);
                            const int p = (col & (HD - 1)) >> 1;
                            float f = __ldg(freqs + s * (HD / 2) + p);
                            float sn, cs;
                            sincosf(f, &sn, &cs);
                            float r0 = v0 * cs - v1 * sn;
                            float r1 = v0 * sn + v1 * cs;
                            v0 = r0; v1 = r1;
                        }
                        __nv_bfloat16 h0 = __float2bfloat16(v0);
                        __nv_bfloat16 h1 = __float2bfloat16(v1);
                        const size_t o = (size_t)row * N + col;
                        *(uint32_t*)(Chi + o) = packbf2(h0, h1);
                        *(uint32_t*)(Clo + o) = packbf2(
                            __float2bfloat16(v0 - __bfloat162float(h0)),
                            __float2bfloat16(v1 - __bfloat162float(h1)));
                    }
                }
            }
        }
        __syncthreads();   // all epilogue reads of regs done; smem reuse safe
    }
}

// ---------------------------------------------------------------------------
// fp32 -> bf16 hi/lo elementwise (for x)
// ---------------------------------------------------------------------------
__global__ void convert_hilo_kernel(const float* __restrict__ in,
                                    __nv_bfloat16* __restrict__ hi,
                                    __nv_bfloat16* __restrict__ lo, int n)
{
    int i = blockIdx.x * blockDim.x + threadIdx.x;
    if (i >= n) return;
    float v = in[i];
    __nv_bfloat16 h = __float2bfloat16(v);
    hi[i] = h;
    lo[i] = __float2bfloat16(v - __bfloat162float(h));
}

// ---------------------------------------------------------------------------
// W [Kd,Nd] fp32 -> Wt hi/lo [Nd,Kd] bf16 (tiled transpose)
// ---------------------------------------------------------------------------
__global__ void transpose_hilo_kernel(const float* __restrict__ W,
                                      __nv_bfloat16* __restrict__ hi,
                                      __nv_bfloat16* __restrict__ lo,
                                      int Kd, int Nd)
{
    __shared__ float t[32][33];
    const int tx = threadIdx.x, ty = threadIdx.y;
    const int k0 = blockIdx.y * 32, n0 = blockIdx.x * 32;
#pragma unroll
    for (int i = 0; i < 4; i++)
        t[ty + i * 8][tx] = W[(size_t)(k0 + ty + i * 8) * Nd + n0 + tx];
    __syncthreads();
#pragma unroll
    for (int i = 0; i < 4; i++) {
        float v = t[tx][ty + i * 8];
        __nv_bfloat16 h = __float2bfloat16(v);
        size_t o = (size_t)(n0 + ty + i * 8) * Kd + k0 + tx;
        hi[o] = h;
        lo[o] = __float2bfloat16(v - __bfloat162float(h));
    }
}

// ---------------------------------------------------------------------------
// HMMA causal flash attention, bf16 hi/lo (3-term QK and PV), fp32 softmax.
// BR=BC=64, 128 threads (4 warps x 16 q-rows). Single-buffered K/V smem
// (104KB => 2 CTAs/SM). K and V read from the merged KV buffer (stride 4096,
// V at column offset 2048). Unchanged math from round 6.
// ---------------------------------------------------------------------------
#define FP   136
#define FPB  272
#define FT   17408
#define SQHI 0
#define SQLO 17408
#define SKHI 34816
#define SKLO 52224
#define SVHI 69632
#define SVLO 87040
#define FL_SMEM 104448

__global__ __launch_bounds__(128)
void flash_hmma_kernel(const __nv_bfloat16* __restrict__ Qhi,
                       const __nv_bfloat16* __restrict__ Qlo,
                       const __nv_bfloat16* __restrict__ KVhi,
                       const __nv_bfloat16* __restrict__ KVlo,
                       __nv_bfloat16* __restrict__ Ohi,
                       __nv_bfloat16* __restrict__ Olo)
{
    extern __shared__ char dsm[];
    const uint32_t sb = smem_u32(dsm);

    const int tid = threadIdx.x, lane = tid & 31, wm = tid >> 5;
    const int lr = lane >> 2, lc2 = (lane & 3) * 2;

    const int bh_ = blockIdx.y;
    const int b = bh_ >> 4, head = bh_ & 15;
    const int qi = gridDim.x - 1 - blockIdx.x;       // heavy blocks first
    const int q0 = qi * 64;
    const size_t baseQ  = ((size_t)b * S_LEN) * D_DIM + head * HD;
    const size_t baseKV = ((size_t)b * S_LEN) * KV_W + head * HD;

#pragma unroll
    for (int j = 0; j < 8; j++) {
        int lin = j * 128 + tid;
        int row = lin >> 4, c16 = lin & 15;
        const size_t so = baseQ + (size_t)(q0 + row) * D_DIM + c16 * 8;
        const uint32_t doff = row * FPB + c16 * 16;
        cp16(sb + SQHI + doff, Qhi + so);
        cp16(sb + SQLO + doff, Qlo + so);
    }
    CP_COMMIT();

    float m[2] = {-1e30f, -1e30f}, l[2] = {0.f, 0.f};
    float accO[16][4];
#pragma unroll
    for (int nt = 0; nt < 16; nt++)
#pragma unroll
        for (int e = 0; e < 4; e++) accO[nt][e] = 0.f;

    const float scale = 0.08838834764831845f;
    const int qrow_base = q0 + wm * 16;

    for (int kt = 0; kt <= qi; kt++) {
        const int k0g = kt * 64;
        __syncthreads();
#pragma unroll
        for (int j = 0; j < 8; j++) {
            int lin = j * 128 + tid;
            int row = lin >> 4, c16 = lin & 15;
            const size_t so = baseKV + (size_t)(k0g + row) * KV_W + c16 * 8;
            const uint32_t doff = row * FPB + c16 * 16;
            cp16(sb + SKHI + doff, KVhi + so);
            cp16(sb + SKLO + doff, KVlo + so);
            cp16(sb + SVHI + doff, KVhi + so + 2048);
            cp16(sb + SVLO + doff, KVlo + so + 2048);
        }
        CP_COMMIT();
        asm volatile("cp.async.wait_group 0;" ::: "memory");
        __syncthreads();

        float accS[8][4];
#pragma unroll
        for (int n = 0; n < 8; n++)
#pragma unroll
            for (int e = 0; e < 4; e++) accS[n][e] = 0.f;

#pragma unroll
        for (int ks = 0; ks < 8; ks++) {
            const int kk = ks * 16;
            uint32_t qh[4], ql[4];
            const uint32_t qoff = (wm * 16 + (lane & 15)) * FPB
                                  + (kk + ((lane >> 4) << 3)) * 2;
            ldsm4(qh[0], qh[1], qh[2], qh[3], sb + SQHI + qoff);
            ldsm4(ql[0], ql[1], ql[2], ql[3], sb + SQLO + qoff);
#pragma unroll
            for (int np = 0; np < 4; np++) {
                const uint32_t koff =
                    (np * 16 + (lane & 7) + ((lane >> 4) << 3)) * FPB
                    + (kk + (((lane >> 3) & 1) << 3)) * 2;
                uint32_t bh[4], bl[4];
                ldsm4(bh[0], bh[1], bh[2], bh[3], sb + SKHI + koff);
                ldsm4(bl[0], bl[1], bl[2], bl[3], sb + SKLO + koff);
#pragma unroll
                for (int t = 0; t < 2; t++)
                    mma16816(accS[np * 2 + t], qh, bh[2 * t], bh[2 * t + 1]);
#pragma unroll
                for (int t = 0; t < 2; t++)
                    mma16816(accS[np * 2 + t], qh, bl[2 * t], bl[2 * t + 1]);
#pragma unroll
                for (int t = 0; t < 2; t++)
                    mma16816(accS[np * 2 + t], ql, bh[2 * t], bh[2 * t + 1]);
            }
        }

        const bool diag = (kt == qi);
#pragma unroll
        for (int n = 0; n < 8; n++) {
#pragma unroll
            for (int e = 0; e < 4; e++) {
                float v = accS[n][e] * scale;
                if (diag) {
                    int row = qrow_base + lr + 8 * (e >> 1);
                    int col = k0g + n * 8 + lc2 + (e & 1);
                    if (col > row) v = -1e30f;
                }
                accS[n][e] = v;
            }
        }

#pragma unroll
        for (int h = 0; h < 2; h++) {
            float mt = -1e30f;
#pragma unroll
            for (int n = 0; n < 8; n++)
                mt = fmaxf(mt, fmaxf(accS[n][2 * h], accS[n][2 * h + 1]));
            mt = fmaxf(mt, __shfl_xor_sync(0xffffffffu, mt, 1));
            mt = fmaxf(mt, __shfl_xor_sync(0xffffffffu, mt, 2));
            float mn = fmaxf(m[h], mt);
            float alpha = __expf(m[h] - mn);
            m[h] = mn;
            float lt = 0.f;
#pragma unroll
            for (int n = 0; n < 8; n++) {
                float p0 = __expf(accS[n][2 * h] - mn);
                float p1 = __expf(accS[n][2 * h + 1] - mn);
                accS[n][2 * h] = p0;
                accS[n][2 * h + 1] = p1;
                lt += p0 + p1;
            }
            lt += __shfl_xor_sync(0xffffffffu, lt, 1);
            lt += __shfl_xor_sync(0xffffffffu, lt, 2);
            l[h] = l[h] * alpha + lt;
#pragma unroll
            for (int nt = 0; nt < 16; nt++) {
                accO[nt][2 * h] *= alpha;
                accO[nt][2 * h + 1] *= alpha;
            }
        }

#pragma unroll
        for (int t = 0; t < 4; t++) {
            uint32_t phi[4], plo[4];
#pragma unroll
            for (int half = 0; half < 2; half++) {
                float* s = accS[2 * t + half];
#pragma unroll
                for (int rh = 0; rh < 2; rh++) {
                    float v0 = s[2 * rh], v1 = s[2 * rh + 1];
                    __nv_bfloat16 h0 = __float2bfloat16(v0);
                    __nv_bfloat16 h1 = __float2bfloat16(v1);
                    phi[half * 2 + rh] = packbf2(h0, h1);
                    plo[half * 2 + rh] = packbf2(
                        __float2bfloat16(v0 - __bfloat162float(h0)),
                        __float2bfloat16(v1 - __bfloat162float(h1)));
                }
            }
            const int kk = t * 16;
#pragma unroll
            for (int np = 0; np < 8; np++) {
                const uint32_t voff = (kk + (lane & 15)) * FPB
                                      + (np * 16 + ((lane >> 4) << 3)) * 2;
                uint32_t vh[4], vl[4];
                ldsm4t(vh[0], vh[1], vh[2], vh[3], sb + SVHI + voff);
                ldsm4t(vl[0], vl[1], vl[2], vl[3], sb + SVLO + voff);
#pragma unroll
                for (int u = 0; u < 2; u++)
                    mma16816(accO[np * 2 + u], phi, vh[2 * u], vh[2 * u + 1]);
#pragma unroll
                for (int u = 0; u < 2; u++)
                    mma16816(accO[np * 2 + u], phi, vl[2 * u], vl[2 * u + 1]);
#pragma unroll
                for (int u = 0; u < 2; u++)
                    mma16816(accO[np * 2 + u], plo, vh[2 * u], vh[2 * u + 1]);
            }
        }
    }

    const float inv0 = 1.0f / l[0], inv1 = 1.0f / l[1];
#pragma unroll
    for (int nt = 0; nt < 16; nt++) {
#pragma unroll
        for (int h = 0; h < 2; h++) {
            float inv = h ? inv1 : inv0;
            float v0 = accO[nt][2 * h] * inv;
            float v1 = accO[nt][2 * h + 1] * inv;
            __nv_bfloat16 h0 = __float2bfloat16(v0);
            __nv_bfloat16 h1 = __float2bfloat16(v1);
            const size_t o = baseQ
                + (size_t)(qrow_base + lr + 8 * h) * D_DIM + nt * 8 + lc2;
            *(uint32_t*)(Ohi + o) = packbf2(h0, h1);
            *(uint32_t*)(Olo + o) = packbf2(
                __float2bfloat16(v0 - __bfloat162float(h0)),
                __float2bfloat16(v1 - __bfloat162float(h1)));
        }
    }
}

// ---------------------------------------------------------------------------
// Launch
// Inputs: x, freqs, mask(unused: exactly causal), Wq, Wdown, Wkup, Wvup, Wo
// ---------------------------------------------------------------------------
extern "C" void kernel_launch(void* const* d_in, const int* in_sizes, int n_in,
                              void* d_out, int out_size)
{
    const float* x     = (const float*)d_in[0];
    const float* freqs = (const float*)d_in[1];
    const float* Wq    = (const float*)d_in[3];
    const float* Wdn   = (const float*)d_in[4];
    const float* Wku   = (const float*)d_in[5];
    const float* Wvu   = (const float*)d_in[6];
    const float* Wo    = (const float*)d_in[7];
    float* out = (float*)d_out;

    __nv_bfloat16 *xhi, *xlo, *chi, *clo, *wthi, *wtlo;
    __nv_bfloat16 *qhi, *qlo, *kvhi, *kvlo, *ohi, *olo;
    cudaGetSymbolAddress((void**)&xhi, g_xhi);
    cudaGetSymbolAddress((void**)&xlo, g_xlo);
    cudaGetSymbolAddress((void**)&chi, g_chi);
    cudaGetSymbolAddress((void**)&clo, g_clo);
    cudaGetSymbolAddress((void**)&qhi, g_qhi);
    cudaGetSymbolAddress((void**)&qlo, g_qlo);
    cudaGetSymbolAddress((void**)&kvhi, g_kvhi);
    cudaGetSymbolAddress((void**)&kvlo, g_kvlo);
    cudaGetSymbolAddress((void**)&ohi, g_ohi);
    cudaGetSymbolAddress((void**)&olo, g_olo);
    cudaGetSymbolAddress((void**)&wthi, g_wthi);
    cudaGetSymbolAddress((void**)&wtlo, g_wtlo);

    cudaFuncSetAttribute(gemm_hilo_kernel,
                         cudaFuncAttributeMaxDynamicSharedMemorySize, GK_SMEM_DYN);
    cudaFuncSetAttribute(flash_hmma_kernel,
                         cudaFuncAttributeMaxDynamicSharedMemorySize, FL_SMEM);

    // Weight transposes + x conversion (bandwidth-bound)
    dim3 tb(32, 8);
    transpose_hilo_kernel<<<dim3(64, 64), tb>>>(Wq,  wthi + OFF_WQ,  wtlo + OFF_WQ,  2048, 2048);
    transpose_hilo_kernel<<<dim3(16, 64), tb>>>(Wdn, wthi + OFF_WDN, wtlo + OFF_WDN, 2048, 512);
    transpose_hilo_kernel<<<dim3(64, 16), tb>>>(Wku, wthi + OFF_WKU, wtlo + OFF_WKU, 512, 2048);
    transpose_hilo_kernel<<<dim3(64, 16), tb>>>(Wvu, wthi + OFF_WVU, wtlo + OFF_WVU, 512, 2048);
    transpose_hilo_kernel<<<dim3(64, 64), tb>>>(Wo,  wthi + OFF_WO,  wtlo + OFF_WO,  2048, 2048);

    const int nx = ROWS_TOT * D_DIM;
    convert_hilo_kernel<<<nx / 256, 256>>>(x, xhi, xlo, nx);

    // Q projection + fused RoPE -> qhi/qlo  (512 tiles, persistent)
    gemm_hilo_kernel<<<GK_GRID, 256, GK_SMEM_DYN>>>(
        xhi, xlo, wthi + OFF_WQ, wtlo + OFF_WQ,
        nullptr, qhi, qlo, freqs, D_DIM,
        ROWS_TOT, D_DIM, D_DIM);

    // Latent down-projection -> chi/clo (128 tiles)
    gemm_hilo_kernel<<<128, 256, GK_SMEM_DYN>>>(
        xhi, xlo, wthi + OFF_WDN, wtlo + OFF_WDN,
        nullptr, chi, clo, nullptr, 0,
        ROWS_TOT, LAT, D_DIM);

    // Merged K|V up-projection (N=4096): K half gets RoPE, V half plain.
    gemm_hilo_kernel<<<GK_GRID, 256, GK_SMEM_DYN>>>(
        chi, clo, wthi + OFF_WKU, wtlo + OFF_WKU,
        nullptr, kvhi, kvlo, freqs, 2048,
        ROWS_TOT, KV_W, LAT);

    // Flash attention (causal, HMMA hi/lo) -> O as bf16 hi/lo
    flash_hmma_kernel<<<dim3(S_LEN / 64, BATCH * NH), 128, FL_SMEM>>>(
        qhi, qlo, kvhi, kvlo, ohi, olo);

    // Output projection (fp32 out, persistent)
    gemm_hilo_kernel<<<GK_GRID, 256, GK_SMEM_DYN>>>(
        ohi, olo, wthi + OFF_WO, wtlo + OFF_WO,
        out, nullptr, nullptr, nullptr, 0,
        ROWS_TOT, D_DIM, D_DIM);
}

// round 10
// speedup vs baseline: 1.2516x; 1.0560x over previous
#include <cuda_runtime.h>
#include <cuda_bf16.h>
#include <cstdint>
#include <math.h>

// Problem constants
#define BATCH   2
#define S_LEN   2048
#define D_DIM   2048
#define NH      16
#define HD      128
#define LAT     512
#define ROWS_TOT (BATCH * S_LEN)   // 4096
#define KV_W    4096               // merged K|V row width

// ---------------------------------------------------------------------------
// Scratch (__device__ globals; allocation-free rule)
// ---------------------------------------------------------------------------
__device__ __nv_bfloat16 g_xhi[ROWS_TOT * D_DIM];
__device__ __nv_bfloat16 g_xlo[ROWS_TOT * D_DIM];
__device__ __nv_bfloat16 g_chi[ROWS_TOT * LAT];
__device__ __nv_bfloat16 g_clo[ROWS_TOT * LAT];
__device__ __nv_bfloat16 g_qhi[ROWS_TOT * D_DIM];
__device__ __nv_bfloat16 g_qlo[ROWS_TOT * D_DIM];
__device__ __nv_bfloat16 g_kvhi[ROWS_TOT * KV_W];   // [0,2048)=K(roped), [2048,4096)=V
__device__ __nv_bfloat16 g_kvlo[ROWS_TOT * KV_W];
__device__ __nv_bfloat16 g_ohi[ROWS_TOT * D_DIM];
__device__ __nv_bfloat16 g_olo[ROWS_TOT * D_DIM];

// Transposed-weight pool ([N,K] K-major bf16), hi and lo parts.
#define OFF_WQ  0
#define OFF_WDN 4194304
#define OFF_WKU 5242880
#define OFF_WVU 6291456
#define OFF_WO  7340032
#define WT_TOTAL 11534336
__device__ __nv_bfloat16 g_wthi[WT_TOTAL];
__device__ __nv_bfloat16 g_wtlo[WT_TOTAL];

// ---------------------------------------------------------------------------
// PTX helpers (sm_80+ features only — harness targets plain sm_103)
// ---------------------------------------------------------------------------
__device__ __forceinline__ uint32_t smem_u32(const void* p) {
    uint32_t a;
    asm("{ .reg .u64 t; cvta.to.shared.u64 t, %1; cvt.u32.u64 %0, t; }"
        : "=r"(a) : "l"(p));
    return a;
}
__device__ __forceinline__ void cp16(uint32_t dst, const void* src) {
    asm volatile("cp.async.cg.shared.global [%0], [%1], 16;" :: "r"(dst), "l"(src));
}
#define CP_COMMIT() asm volatile("cp.async.commit_group;" ::: "memory")

__device__ __forceinline__ void ldsm4(uint32_t& r0, uint32_t& r1,
                                      uint32_t& r2, uint32_t& r3, uint32_t a) {
    asm volatile("ldmatrix.sync.aligned.m8n8.x4.shared.b16 {%0,%1,%2,%3}, [%4];"
                 : "=r"(r0), "=r"(r1), "=r"(r2), "=r"(r3) : "r"(a));
}
__device__ __forceinline__ void ldsm4t(uint32_t& r0, uint32_t& r1,
                                       uint32_t& r2, uint32_t& r3, uint32_t a) {
    asm volatile("ldmatrix.sync.aligned.m8n8.x4.trans.shared.b16 {%0,%1,%2,%3}, [%4];"
                 : "=r"(r0), "=r"(r1), "=r"(r2), "=r"(r3) : "r"(a));
}
// Non-volatile: pure register op; lets ptxas interleave MMAs to break
// accumulator RAW chains.
__device__ __forceinline__ void mma16816(float* d, const uint32_t* a,
                                         uint32_t b0, uint32_t b1) {
    asm("mma.sync.aligned.m16n8k16.row.col.f32.bf16.bf16.f32 "
        "{%0,%1,%2,%3}, {%4,%5,%6,%7}, {%8,%9}, {%0,%1,%2,%3};"
        : "+f"(d[0]), "+f"(d[1]), "+f"(d[2]), "+f"(d[3])
        : "r"(a[0]), "r"(a[1]), "r"(a[2]), "r"(a[3]), "r"(b0), "r"(b1));
}
__device__ __forceinline__ uint32_t packbf2(__nv_bfloat16 x, __nv_bfloat16 y) {
    __nv_bfloat162 t(x, y);
    return *(uint32_t*)&t;
}

// XOR chunk swizzle for 64B-pitch rows (4 x 16B chunks per row):
// chunk' = chunk ^ ((row>>1)&3). Conflict-free for ldsm 8-lane phases.
__device__ __forceinline__ uint32_t swz64(int row, int chunk) {
    return (uint32_t)(row * 64 + ((chunk ^ ((row >> 1) & 3)) << 4));
}

// ---------------------------------------------------------------------------
// HMMA bf16 hi/lo GEMM (persistent): C[M,N] = A[M,K] @ Bt[N,K]^T, fp32 acc.
// 128x128x32 CTA tile, 256 thr (8 warps 4x2 of 32x64), term-major MMAs.
// 3-stage cp.async ring: 64B-pitch XOR-swizzled tiles -> 32KB/stage, 96KB
// total => 2 CTAs/SM with wait_group(1) slack (loads get ~2 iters to land).
// Epilogues: fp32 (Cout) or bf16 hi/lo (+optional RoPE on cols < rope_cols).
// ---------------------------------------------------------------------------
#define ST_AHI  0
#define ST_ALO  8192
#define ST_BHI  16384
#define ST_BLO  24576
#define STAGE_B 32768
#define GK_SMEM_DYN (3 * STAGE_B)   // 96 KB
#define GK_GRID 296                 // 2 CTAs x 148 SMs

__global__ __launch_bounds__(256, 2)
void gemm_hilo_kernel(const __nv_bfloat16* __restrict__ Ahi,
                      const __nv_bfloat16* __restrict__ Alo,
                      const __nv_bfloat16* __restrict__ Bhi,
                      const __nv_bfloat16* __restrict__ Blo,
                      float* __restrict__ Cout,
                      __nv_bfloat16* __restrict__ Chi,
                      __nv_bfloat16* __restrict__ Clo,
                      const float* __restrict__ freqs,
                      int rope_cols,
                      int M, int N, int K)
{
    extern __shared__ char dsm[];
    const uint32_t sbase = smem_u32(dsm);
    const int tid = threadIdx.x, lane = tid & 31, wid = tid >> 5;
    const int wm = wid & 3, wn = wid >> 2;           // 4 x 2 warp grid
    const int lrow = tid >> 1;                       // loader row 0..127
    const int lc0  = (tid & 1) * 2;                  // loader chunk 0 or 2
    const int lr = lane >> 2, lc = (lane & 3) * 2;
    const int nk = K >> 5;
    const int ntx = N >> 7;
    const int ntiles = (M >> 7) * ntx;

    for (int tile = blockIdx.x; tile < ntiles; tile += gridDim.x) {
        const int tyi = tile / ntx;
        const int txi = tile - tyi * ntx;
        const int m0 = tyi * 128, n0 = txi * 128;

        const __nv_bfloat16* gAh = Ahi + (size_t)m0 * K;
        const __nv_bfloat16* gAl = Alo + (size_t)m0 * K;
        const __nv_bfloat16* gBh = Bhi + (size_t)n0 * K;
        const __nv_bfloat16* gBl = Blo + (size_t)n0 * K;

        float acc[2][8][4];
#pragma unroll
        for (int mt = 0; mt < 2; mt++)
#pragma unroll
            for (int nt = 0; nt < 8; nt++)
#pragma unroll
                for (int r = 0; r < 4; r++) acc[mt][nt][r] = 0.f;

        auto load_stage = [&](int buf, int kc) {
            const uint32_t st = sbase + buf * STAGE_B;
            const size_t koff = (size_t)kc * 32;
#pragma unroll
            for (int t = 0; t < 2; t++) {
                const int c = lc0 + t;
                const uint32_t doff = swz64(lrow, c);
                const size_t soff = (size_t)lrow * K + koff + c * 8;
                cp16(st + ST_AHI + doff, gAh + soff);
                cp16(st + ST_ALO + doff, gAl + soff);
                cp16(st + ST_BHI + doff, gBh + soff);
                cp16(st + ST_BLO + doff, gBl + soff);
            }
            CP_COMMIT();
        };

        // Prologue: 2 stages in flight.
        load_stage(0, 0);
        if (nk > 1) load_stage(1, 1);

        for (int k = 0; k < nk; k++) {
            // Need group k done; group k+1 may stay in flight.
            if (k + 1 < nk)
                asm volatile("cp.async.wait_group 1;" ::: "memory");
            else
                asm volatile("cp.async.wait_group 0;" ::: "memory");
            __syncthreads();   // stage k visible; iter k-1 compute done

            // Buffer (k+2)%3 == (k-1)%3 was last read in iter k-1 -> free.
            if (k + 2 < nk) load_stage((k + 2) % 3, k + 2);

            const uint32_t st = sbase + (k % 3) * STAGE_B;
#pragma unroll
            for (int ks = 0; ks < 2; ks++) {
                uint32_t ah[2][4], al[2][4];
#pragma unroll
                for (int mt = 0; mt < 2; mt++) {
                    const int row = wm * 32 + mt * 16 + (lane & 15);
                    const uint32_t off = swz64(row, ks * 2 + (lane >> 4));
                    ldsm4(ah[mt][0], ah[mt][1], ah[mt][2], ah[mt][3],
                          st + ST_AHI + off);
                    ldsm4(al[mt][0], al[mt][1], al[mt][2], al[mt][3],
                          st + ST_ALO + off);
                }
#pragma unroll
                for (int bp = 0; bp < 4; bp++) {
                    const int rn = wn * 64 + bp * 16 + ((lane >> 4) << 3) + (lane & 7);
                    const uint32_t off = swz64(rn, ks * 2 + ((lane >> 3) & 1));
                    uint32_t bh[4], bl[4];
                    ldsm4(bh[0], bh[1], bh[2], bh[3], st + ST_BHI + off);
                    ldsm4(bl[0], bl[1], bl[2], bl[3], st + ST_BLO + off);
                    // term-major: 4 independent accumulators between reuse
#pragma unroll
                    for (int mt = 0; mt < 2; mt++)
#pragma unroll
                        for (int h = 0; h < 2; h++)
                            mma16816(acc[mt][2 * bp + h], ah[mt], bh[2 * h], bh[2 * h + 1]);
#pragma unroll
                    for (int mt = 0; mt < 2; mt++)
#pragma unroll
                        for (int h = 0; h < 2; h++)
                            mma16816(acc[mt][2 * bp + h], ah[mt], bl[2 * h], bl[2 * h + 1]);
#pragma unroll
                    for (int mt = 0; mt < 2; mt++)
#pragma unroll
                        for (int h = 0; h < 2; h++)
                            mma16816(acc[mt][2 * bp + h], al[mt], bh[2 * h], bh[2 * h + 1]);
                }
            }
        }

        const int rbase = m0 + wm * 32, cbase = n0 + wn * 64;
        if (Cout) {
#pragma unroll
            for (int mt = 0; mt < 2; mt++) {
#pragma unroll
                for (int nt = 0; nt < 8; nt++) {
                    float* d = acc[mt][nt];
                    const size_t r0 = (size_t)(rbase + mt * 16 + lr) * N
                                      + cbase + nt * 8 + lc;
                    *(float2*)(Cout + r0)         = make_float2(d[0], d[1]);
                    *(float2*)(Cout + r0 + 8 * N) = make_float2(d[2], d[3]);
                }
            }
        } else {
            const bool do_rope = (freqs != nullptr) && (cbase < rope_cols);
#pragma unroll
            for (int mt = 0; mt < 2; mt++) {
#pragma unroll
                for (int nt = 0; nt < 8; nt++) {
                    float* d = acc[mt][nt];
#pragma unroll
                    for (int half = 0; half < 2; half++) {
                        const int row = rbase + mt * 16 + lr + half * 8;
                        const int col = cbase + nt * 8 + lc;
                        float v0 = d[half * 2], v1 = d[half * 2 + 1];
                        if (do_rope) {
                            const int s = row & (S_LEN - 1);
                            const int p = (col & (HD - 1)) >> 1;
                            float f = __ldg(freqs + s * (HD / 2) + p);
                            float sn, cs;
                            sincosf(f, &sn, &cs);
                            float r0 = v0 * cs - v1 * sn;
                            float r1 = v0 * sn + v1 * cs;
                            v0 = r0; v1 = r1;
                        }
                        __nv_bfloat16 h0 = __float2bfloat16(v0);
                        __nv_bfloat16 h1 = __float2bfloat16(v1);
                        const size_t o = (size_t)row * N + col;
                        *(uint32_t*)(Chi + o) = packbf2(h0, h1);
                        *(uint32_t*)(Clo + o) = packbf2(
                            __float2bfloat16(v0 - __bfloat162float(h0)),
                            __float2bfloat16(v1 - __bfloat162float(h1)));
                    }
                }
            }
        }
        __syncthreads();   // epilogue done; smem reuse by next tile safe
    }
}

// ---------------------------------------------------------------------------
// fp32 -> bf16 hi/lo elementwise (for x)
// ---------------------------------------------------------------------------
__global__ void convert_hilo_kernel(const float* __restrict__ in,
                                    __nv_bfloat16* __restrict__ hi,
                                    __nv_bfloat16* __restrict__ lo, int n)
{
    int i = blockIdx.x * blockDim.x + threadIdx.x;
    if (i >= n) return;
    float v = in[i];
    __nv_bfloat16 h = __float2bfloat16(v);
    hi[i] = h;
    lo[i] = __float2bfloat16(v - __bfloat162float(h));
}

// ---------------------------------------------------------------------------
// W [Kd,Nd] fp32 -> Wt hi/lo [Nd,Kd] bf16 (tiled transpose)
// ---------------------------------------------------------------------------
__global__ void transpose_hilo_kernel(const float* __restrict__ W,
                                      __nv_bfloat16* __restrict__ hi,
                                      __nv_bfloat16* __restrict__ lo,
                                      int Kd, int Nd)
{
    __shared__ float t[32][33];
    const int tx = threadIdx.x, ty = threadIdx.y;
    const int k0 = blockIdx.y * 32, n0 = blockIdx.x * 32;
#pragma unroll
    for (int i = 0; i < 4; i++)
        t[ty + i * 8][tx] = W[(size_t)(k0 + ty + i * 8) * Nd + n0 + tx];
    __syncthreads();
#pragma unroll
    for (int i = 0; i < 4; i++) {
        float v = t[tx][ty + i * 8];
        __nv_bfloat16 h = __float2bfloat16(v);
        size_t o = (size_t)(n0 + ty + i * 8) * Kd + k0 + tx;
        hi[o] = h;
        lo[o] = __float2bfloat16(v - __bfloat162float(h));
    }
}

// ---------------------------------------------------------------------------
// HMMA causal flash attention, bf16 hi/lo (3-term QK and PV), fp32 softmax.
// BR=BC=64, 128 threads (4 warps x 16 q-rows). Single-buffered K/V smem
// (104KB => 2 CTAs/SM). K/V read from merged KV buffer (stride 4096, V at
// column offset 2048). Unchanged math from round 6/9 (known-good).
// ---------------------------------------------------------------------------
#define FP   136
#define FPB  272
#define FT   17408
#define SQHI 0
#define SQLO 17408
#define SKHI 34816
#define SKLO 52224
#define SVHI 69632
#define SVLO 87040
#define FL_SMEM 104448

__global__ __launch_bounds__(128)
void flash_hmma_kernel(const __nv_bfloat16* __restrict__ Qhi,
                       const __nv_bfloat16* __restrict__ Qlo,
                       const __nv_bfloat16* __restrict__ KVhi,
                       const __nv_bfloat16* __restrict__ KVlo,
                       __nv_bfloat16* __restrict__ Ohi,
                       __nv_bfloat16* __restrict__ Olo)
{
    extern __shared__ char dsm[];
    const uint32_t sb = smem_u32(dsm);

    const int tid = threadIdx.x, lane = tid & 31, wm = tid >> 5;
    const int lr = lane >> 2, lc2 = (lane & 3) * 2;

    const int bh_ = blockIdx.y;
    const int b = bh_ >> 4, head = bh_ & 15;
    const int qi = gridDim.x - 1 - blockIdx.x;       // heavy blocks first
    const int q0 = qi * 64;
    const size_t baseQ  = ((size_t)b * S_LEN) * D_DIM + head * HD;
    const size_t baseKV = ((size_t)b * S_LEN) * KV_W + head * HD;

#pragma unroll
    for (int j = 0; j < 8; j++) {
        int lin = j * 128 + tid;
        int row = lin >> 4, c16 = lin & 15;
        const size_t so = baseQ + (size_t)(q0 + row) * D_DIM + c16 * 8;
        const uint32_t doff = row * FPB + c16 * 16;
        cp16(sb + SQHI + doff, Qhi + so);
        cp16(sb + SQLO + doff, Qlo + so);
    }
    CP_COMMIT();

    float m[2] = {-1e30f, -1e30f}, l[2] = {0.f, 0.f};
    float accO[16][4];
#pragma unroll
    for (int nt = 0; nt < 16; nt++)
#pragma unroll
        for (int e = 0; e < 4; e++) accO[nt][e] = 0.f;

    const float scale = 0.08838834764831845f;
    const int qrow_base = q0 + wm * 16;

    for (int kt = 0; kt <= qi; kt++) {
        const int k0g = kt * 64;
        __syncthreads();
#pragma unroll
        for (int j = 0; j < 8; j++) {
            int lin = j * 128 + tid;
            int row = lin >> 4, c16 = lin & 15;
            const size_t so = baseKV + (size_t)(k0g + row) * KV_W + c16 * 8;
            const uint32_t doff = row * FPB + c16 * 16;
            cp16(sb + SKHI + doff, KVhi + so);
            cp16(sb + SKLO + doff, KVlo + so);
            cp16(sb + SVHI + doff, KVhi + so + 2048);
            cp16(sb + SVLO + doff, KVlo + so + 2048);
        }
        CP_COMMIT();
        asm volatile("cp.async.wait_group 0;" ::: "memory");
        __syncthreads();

        float accS[8][4];
#pragma unroll
        for (int n = 0; n < 8; n++)
#pragma unroll
            for (int e = 0; e < 4; e++) accS[n][e] = 0.f;

#pragma unroll
        for (int ks = 0; ks < 8; ks++) {
            const int kk = ks * 16;
            uint32_t qh[4], ql[4];
            const uint32_t qoff = (wm * 16 + (lane & 15)) * FPB
                                  + (kk + ((lane >> 4) << 3)) * 2;
            ldsm4(qh[0], qh[1], qh[2], qh[3], sb + SQHI + qoff);
            ldsm4(ql[0], ql[1], ql[2], ql[3], sb + SQLO + qoff);
#pragma unroll
            for (int np = 0; np < 4; np++) {
                const uint32_t koff =
                    (np * 16 + (lane & 7) + ((lane >> 4) << 3)) * FPB
                    + (kk + (((lane >> 3) & 1) << 3)) * 2;
                uint32_t bh[4], bl[4];
                ldsm4(bh[0], bh[1], bh[2], bh[3], sb + SKHI + koff);
                ldsm4(bl[0], bl[1], bl[2], bl[3], sb + SKLO + koff);
#pragma unroll
                for (int t = 0; t < 2; t++)
                    mma16816(accS[np * 2 + t], qh, bh[2 * t], bh[2 * t + 1]);
#pragma unroll
                for (int t = 0; t < 2; t++)
                    mma16816(accS[np * 2 + t], qh, bl[2 * t], bl[2 * t + 1]);
#pragma unroll
                for (int t = 0; t < 2; t++)
                    mma16816(accS[np * 2 + t], ql, bh[2 * t], bh[2 * t + 1]);
            }
        }

        const bool diag = (kt == qi);
#pragma unroll
        for (int n = 0; n < 8; n++) {
#pragma unroll
            for (int e = 0; e < 4; e++) {
                float v = accS[n][e] * scale;
                if (diag) {
                    int row = qrow_base + lr + 8 * (e >> 1);
                    int col = k0g + n * 8 + lc2 + (e & 1);
                    if (col > row) v = -1e30f;
                }
                accS[n][e] = v;
            }
        }

#pragma unroll
        for (int h = 0; h < 2; h++) {
            float mt = -1e30f;
#pragma unroll
            for (int n = 0; n < 8; n++)
                mt = fmaxf(mt, fmaxf(accS[n][2 * h], accS[n][2 * h + 1]));
            mt = fmaxf(mt, __shfl_xor_sync(0xffffffffu, mt, 1));
            mt = fmaxf(mt, __shfl_xor_sync(0xffffffffu, mt, 2));
            float mn = fmaxf(m[h], mt);
            float alpha = __expf(m[h] - mn);
            m[h] = mn;
            float lt = 0.f;
#pragma unroll
            for (int n = 0; n < 8; n++) {
                float p0 = __expf(accS[n][2 * h] - mn);
                float p1 = __expf(accS[n][2 * h + 1] - mn);
                accS[n][2 * h] = p0;
                accS[n][2 * h + 1] = p1;
                lt += p0 + p1;
            }
            lt += __shfl_xor_sync(0xffffffffu, lt, 1);
            lt += __shfl_xor_sync(0xffffffffu, lt, 2);
            l[h] = l[h] * alpha + lt;
#pragma unroll
            for (int nt = 0; nt < 16; nt++) {
                accO[nt][2 * h] *= alpha;
                accO[nt][2 * h + 1] *= alpha;
            }
        }

#pragma unroll
        for (int t = 0; t < 4; t++) {
            uint32_t phi[4], plo[4];
#pragma unroll
            for (int half = 0; half < 2; half++) {
                float* s = accS[2 * t + half];
#pragma unroll
                for (int rh = 0; rh < 2; rh++) {
                    float v0 = s[2 * rh], v1 = s[2 * rh + 1];
                    __nv_bfloat16 h0 = __float2bfloat16(v0);
                    __nv_bfloat16 h1 = __float2bfloat16(v1);
                    phi[half * 2 + rh] = packbf2(h0, h1);
                    plo[half * 2 + rh] = packbf2(
                        __float2bfloat16(v0 - __bfloat162float(h0)),
                        __float2bfloat16(v1 - __bfloat162float(h1)));
                }
            }
            const int kk = t * 16;
#pragma unroll
            for (int np = 0; np < 8; np++) {
                const uint32_t voff = (kk + (lane & 15)) * FPB
                                      + (np * 16 + ((lane >> 4) << 3)) * 2;
                uint32_t vh[4], vl[4];
                ldsm4t(vh[0], vh[1], vh[2], vh[3], sb + SVHI + voff);
                ldsm4t(vl[0], vl[1], vl[2], vl[3], sb + SVLO + voff);
#pragma unroll
                for (int u = 0; u < 2; u++)
                    mma16816(accO[np * 2 + u], phi, vh[2 * u], vh[2 * u + 1]);
#pragma unroll
                for (int u = 0; u < 2; u++)
                    mma16816(accO[np * 2 + u], phi, vl[2 * u], vl[2 * u + 1]);
#pragma unroll
                for (int u = 0; u < 2; u++)
                    mma16816(accO[np * 2 + u], plo, vh[2 * u], vh[2 * u + 1]);
            }
        }
    }

    const float inv0 = 1.0f / l[0], inv1 = 1.0f / l[1];
#pragma unroll
    for (int nt = 0; nt < 16; nt++) {
#pragma unroll
        for (int h = 0; h < 2; h++) {
            float inv = h ? inv1 : inv0;
            float v0 = accO[nt][2 * h] * inv;
            float v1 = accO[nt][2 * h + 1] * inv;
            __nv_bfloat16 h0 = __float2bfloat16(v0);
            __nv_bfloat16 h1 = __float2bfloat16(v1);
            const size_t o = baseQ
                + (size_t)(qrow_base + lr + 8 * h) * D_DIM + nt * 8 + lc2;
            *(uint32_t*)(Ohi + o) = packbf2(h0, h1);
            *(uint32_t*)(Olo + o) = packbf2(
                __float2bfloat16(v0 - __bfloat162float(h0)),
                __float2bfloat16(v1 - __bfloat162float(h1)));
        }
    }
}

// ---------------------------------------------------------------------------
// Launch. Order chosen so the Wq GEMM sits at launch index 4, where the
// ncu -s5 -c1 capture window has been landing (profiling visibility).
// Inputs: x, freqs, mask(unused: exactly causal), Wq, Wdown, Wkup, Wvup, Wo
// ---------------------------------------------------------------------------
extern "C" void kernel_launch(void* const* d_in, const int* in_sizes, int n_in,
                              void* d_out, int out_size)
{
    const float* x     = (const float*)d_in[0];
    const float* freqs = (const float*)d_in[1];
    const float* Wq    = (const float*)d_in[3];
    const float* Wdn   = (const float*)d_in[4];
    const float* Wku   = (const float*)d_in[5];
    const float* Wvu   = (const float*)d_in[6];
    const float* Wo    = (const float*)d_in[7];
    float* out = (float*)d_out;

    __nv_bfloat16 *xhi, *xlo, *chi, *clo, *wthi, *wtlo;
    __nv_bfloat16 *qhi, *qlo, *kvhi, *kvlo, *ohi, *olo;
    cudaGetSymbolAddress((void**)&xhi, g_xhi);
    cudaGetSymbolAddress((void**)&xlo, g_xlo);
    cudaGetSymbolAddress((void**)&chi, g_chi);
    cudaGetSymbolAddress((void**)&clo, g_clo);
    cudaGetSymbolAddress((void**)&qhi, g_qhi);
    cudaGetSymbolAddress((void**)&qlo, g_qlo);
    cudaGetSymbolAddress((void**)&kvhi, g_kvhi);
    cudaGetSymbolAddress((void**)&kvlo, g_kvlo);
    cudaGetSymbolAddress((void**)&ohi, g_ohi);
    cudaGetSymbolAddress((void**)&olo, g_olo);
    cudaGetSymbolAddress((void**)&wthi, g_wthi);
    cudaGetSymbolAddress((void**)&wtlo, g_wtlo);

    cudaFuncSetAttribute(gemm_hilo_kernel,
                         cudaFuncAttributeMaxDynamicSharedMemorySize, GK_SMEM_DYN);
    cudaFuncSetAttribute(flash_hmma_kernel,
                         cudaFuncAttributeMaxDynamicSharedMemorySize, FL_SMEM);

    dim3 tb(32, 8);
    const int nx = ROWS_TOT * D_DIM;

    // idx 0: Wq transpose
    transpose_hilo_kernel<<<dim3(64, 64), tb>>>(Wq,  wthi + OFF_WQ,  wtlo + OFF_WQ,  2048, 2048);
    // idx 1: x hi/lo convert
    convert_hilo_kernel<<<nx / 256, 256>>>(x, xhi, xlo, nx);
    // idx 2,3: small transposes
    transpose_hilo_kernel<<<dim3(16, 64), tb>>>(Wdn, wthi + OFF_WDN, wtlo + OFF_WDN, 2048, 512);
    transpose_hilo_kernel<<<dim3(64, 16), tb>>>(Wku, wthi + OFF_WKU, wtlo + OFF_WKU, 512, 2048);
    // idx 4: Q projection + fused RoPE (the launch we want profiled)
    gemm_hilo_kernel<<<GK_GRID, 256, GK_SMEM_DYN>>>(
        xhi, xlo, wthi + OFF_WQ, wtlo + OFF_WQ,
        nullptr, qhi, qlo, freqs, D_DIM,
        ROWS_TOT, D_DIM, D_DIM);
    // idx 5,6: remaining transposes
    transpose_hilo_kernel<<<dim3(64, 16), tb>>>(Wvu, wthi + OFF_WVU, wtlo + OFF_WVU, 512, 2048);
    transpose_hilo_kernel<<<dim3(64, 64), tb>>>(Wo,  wthi + OFF_WO,  wtlo + OFF_WO,  2048, 2048);
    // idx 7: latent down-projection
    gemm_hilo_kernel<<<128, 256, GK_SMEM_DYN>>>(
        xhi, xlo, wthi + OFF_WDN, wtlo + OFF_WDN,
        nullptr, chi, clo, nullptr, 0,
        ROWS_TOT, LAT, D_DIM);
    // idx 8: merged K|V up-projection (K half roped)
    gemm_hilo_kernel<<<GK_GRID, 256, GK_SMEM_DYN>>>(
        chi, clo, wthi + OFF_WKU, wtlo + OFF_WKU,
        nullptr, kvhi, kvlo, freqs, 2048,
        ROWS_TOT, KV_W, LAT);
    // idx 9: flash attention
    flash_hmma_kernel<<<dim3(S_LEN / 64, BATCH * NH), 128, FL_SMEM>>>(
        qhi, qlo, kvhi, kvlo, ohi, olo);
    // idx 10: output projection (fp32)
    gemm_hilo_kernel<<<GK_GRID, 256, GK_SMEM_DYN>>>(
        ohi, olo, wthi + OFF_WO, wtlo + OFF_WO,
        out, nullptr, nullptr, nullptr, 0,
        ROWS_TOT, D_DIM, D_DIM);
}

// round 11
// speedup vs baseline: 1.2694x; 1.0142x over previous
#include <cuda_runtime.h>
#include <cuda_bf16.h>
#include <cstdint>
#include <math.h>

// Problem constants
#define BATCH   2
#define S_LEN   2048
#define D_DIM   2048
#define NH      16
#define HD      128
#define LAT     512
#define ROWS_TOT (BATCH * S_LEN)   // 4096
#define KV_W    4096               // merged K|V row width
#define QC_W    2560               // merged Q|c row width (2048 Q + 512 c)

// ---------------------------------------------------------------------------
// Scratch (__device__ globals; allocation-free rule)
// ---------------------------------------------------------------------------
__device__ __nv_bfloat16 g_xhi[ROWS_TOT * D_DIM];
__device__ __nv_bfloat16 g_xlo[ROWS_TOT * D_DIM];
__device__ __nv_bfloat16 g_qchi[ROWS_TOT * QC_W];   // [0,2048)=Q(roped), [2048,2560)=c
__device__ __nv_bfloat16 g_qclo[ROWS_TOT * QC_W];
__device__ __nv_bfloat16 g_kvhi[ROWS_TOT * KV_W];   // [0,2048)=K(roped), [2048,4096)=V
__device__ __nv_bfloat16 g_kvlo[ROWS_TOT * KV_W];
__device__ __nv_bfloat16 g_ohi[ROWS_TOT * D_DIM];
__device__ __nv_bfloat16 g_olo[ROWS_TOT * D_DIM];

// Transposed-weight pool ([N,K] K-major bf16), hi and lo parts.
// Layout: [Wq^T 2048x2048][Wdn^T 512x2048][Wku^T 2048x512][Wvu^T 2048x512][Wo^T]
// Wq^T and Wdn^T contiguous -> merged Q|c GEMM B (2560 rows, K=2048).
// Wku^T and Wvu^T contiguous -> merged K|V GEMM B (4096 rows, K=512).
#define OFF_WQ  0
#define OFF_WDN 4194304
#define OFF_WKU 5242880
#define OFF_WVU 6291456
#define OFF_WO  7340032
#define WT_TOTAL 11534336
__device__ __nv_bfloat16 g_wthi[WT_TOTAL];
__device__ __nv_bfloat16 g_wtlo[WT_TOTAL];

// ---------------------------------------------------------------------------
// PTX helpers (sm_80+ features only — harness targets plain sm_103)
// ---------------------------------------------------------------------------
__device__ __forceinline__ uint32_t smem_u32(const void* p) {
    uint32_t a;
    asm("{ .reg .u64 t; cvta.to.shared.u64 t, %1; cvt.u32.u64 %0, t; }"
        : "=r"(a) : "l"(p));
    return a;
}
__device__ __forceinline__ void cp16(uint32_t dst, const void* src) {
    asm volatile("cp.async.cg.shared.global [%0], [%1], 16;" :: "r"(dst), "l"(src));
}
#define CP_COMMIT() asm volatile("cp.async.commit_group;" ::: "memory")

__device__ __forceinline__ void ldsm4(uint32_t& r0, uint32_t& r1,
                                      uint32_t& r2, uint32_t& r3, uint32_t a) {
    asm volatile("ldmatrix.sync.aligned.m8n8.x4.shared.b16 {%0,%1,%2,%3}, [%4];"
                 : "=r"(r0), "=r"(r1), "=r"(r2), "=r"(r3) : "r"(a));
}
__device__ __forceinline__ void ldsm4t(uint32_t& r0, uint32_t& r1,
                                       uint32_t& r2, uint32_t& r3, uint32_t a) {
    asm volatile("ldmatrix.sync.aligned.m8n8.x4.trans.shared.b16 {%0,%1,%2,%3}, [%4];"
                 : "=r"(r0), "=r"(r1), "=r"(r2), "=r"(r3) : "r"(a));
}
// Non-volatile: pure register op; lets ptxas interleave MMAs to break
// accumulator RAW chains.
__device__ __forceinline__ void mma16816(float* d, const uint32_t* a,
                                         uint32_t b0, uint32_t b1) {
    asm("mma.sync.aligned.m16n8k16.row.col.f32.bf16.bf16.f32 "
        "{%0,%1,%2,%3}, {%4,%5,%6,%7}, {%8,%9}, {%0,%1,%2,%3};"
        : "+f"(d[0]), "+f"(d[1]), "+f"(d[2]), "+f"(d[3])
        : "r"(a[0]), "r"(a[1]), "r"(a[2]), "r"(a[3]), "r"(b0), "r"(b1));
}
__device__ __forceinline__ uint32_t packbf2(__nv_bfloat16 x, __nv_bfloat16 y) {
    __nv_bfloat162 t(x, y);
    return *(uint32_t*)&t;
}

// XOR chunk swizzle for 64B-pitch rows (4 x 16B chunks per row):
// chunk' = chunk ^ ((row>>1)&3). Conflict-free for ldsm 8-lane phases.
__device__ __forceinline__ uint32_t swz64(int row, int chunk) {
    return (uint32_t)(row * 64 + ((chunk ^ ((row >> 1) & 3)) << 4));
}

// ---------------------------------------------------------------------------
// HMMA bf16 hi/lo GEMM (persistent): C[M,N] = A[M,K] @ Bt[N,K]^T, fp32 acc.
// 128x128x32 CTA tile, 256 thr (8 warps 4x2 of 32x64), term-major MMAs.
// 3-stage cp.async ring (64B-pitch XOR-swizzled, 32KB/stage, 96KB => 2
// CTAs/SM) with wait_group(1) slack. A row stride = lda, C row stride = ldc
// (B rows always contiguous at stride K). Epilogues: fp32 (Cout) or bf16
// hi/lo with optional RoPE on columns < rope_cols.
// ---------------------------------------------------------------------------
#define ST_AHI  0
#define ST_ALO  8192
#define ST_BHI  16384
#define ST_BLO  24576
#define STAGE_B 32768
#define GK_SMEM_DYN (3 * STAGE_B)   // 96 KB
#define GK_GRID 296                 // 2 CTAs x 148 SMs

__global__ __launch_bounds__(256, 2)
void gemm_hilo_kernel(const __nv_bfloat16* __restrict__ Ahi,
                      const __nv_bfloat16* __restrict__ Alo,
                      const __nv_bfloat16* __restrict__ Bhi,
                      const __nv_bfloat16* __restrict__ Blo,
                      float* __restrict__ Cout,
                      __nv_bfloat16* __restrict__ Chi,
                      __nv_bfloat16* __restrict__ Clo,
                      const float* __restrict__ freqs,
                      int rope_cols,
                      int M, int N, int K, int lda, int ldc)
{
    extern __shared__ char dsm[];
    const uint32_t sbase = smem_u32(dsm);
    const int tid = threadIdx.x, lane = tid & 31, wid = tid >> 5;
    const int wm = wid & 3, wn = wid >> 2;           // 4 x 2 warp grid
    const int lrow = tid >> 1;                       // loader row 0..127
    const int lc0  = (tid & 1) * 2;                  // loader chunk 0 or 2
    const int lr = lane >> 2, lc = (lane & 3) * 2;
    const int nk = K >> 5;
    const int ntx = N >> 7;
    const int ntiles = (M >> 7) * ntx;

    for (int tile = blockIdx.x; tile < ntiles; tile += gridDim.x) {
        const int tyi = tile / ntx;
        const int txi = tile - tyi * ntx;
        const int m0 = tyi * 128, n0 = txi * 128;

        const __nv_bfloat16* gAh = Ahi + (size_t)m0 * lda;
        const __nv_bfloat16* gAl = Alo + (size_t)m0 * lda;
        const __nv_bfloat16* gBh = Bhi + (size_t)n0 * K;
        const __nv_bfloat16* gBl = Blo + (size_t)n0 * K;

        float acc[2][8][4];
#pragma unroll
        for (int mt = 0; mt < 2; mt++)
#pragma unroll
            for (int nt = 0; nt < 8; nt++)
#pragma unroll
                for (int r = 0; r < 4; r++) acc[mt][nt][r] = 0.f;

        auto load_stage = [&](int buf, int kc) {
            const uint32_t st = sbase + buf * STAGE_B;
            const size_t koff = (size_t)kc * 32;
#pragma unroll
            for (int t = 0; t < 2; t++) {
                const int c = lc0 + t;
                const uint32_t doff = swz64(lrow, c);
                cp16(st + ST_AHI + doff, gAh + (size_t)lrow * lda + koff + c * 8);
                cp16(st + ST_ALO + doff, gAl + (size_t)lrow * lda + koff + c * 8);
                cp16(st + ST_BHI + doff, gBh + (size_t)lrow * K + koff + c * 8);
                cp16(st + ST_BLO + doff, gBl + (size_t)lrow * K + koff + c * 8);
            }
            CP_COMMIT();
        };

        // Prologue: 2 stages in flight.
        load_stage(0, 0);
        if (nk > 1) load_stage(1, 1);

        for (int k = 0; k < nk; k++) {
            if (k + 1 < nk)
                asm volatile("cp.async.wait_group 1;" ::: "memory");
            else
                asm volatile("cp.async.wait_group 0;" ::: "memory");
            __syncthreads();   // stage k visible; iter k-1 compute done

            if (k + 2 < nk) load_stage((k + 2) % 3, k + 2);

            const uint32_t st = sbase + (k % 3) * STAGE_B;
#pragma unroll
            for (int ks = 0; ks < 2; ks++) {
                uint32_t ah[2][4], al[2][4];
#pragma unroll
                for (int mt = 0; mt < 2; mt++) {
                    const int row = wm * 32 + mt * 16 + (lane & 15);
                    const uint32_t off = swz64(row, ks * 2 + (lane >> 4));
                    ldsm4(ah[mt][0], ah[mt][1], ah[mt][2], ah[mt][3],
                          st + ST_AHI + off);
                    ldsm4(al[mt][0], al[mt][1], al[mt][2], al[mt][3],
                          st + ST_ALO + off);
                }
#pragma unroll
                for (int bp = 0; bp < 4; bp++) {
                    const int rn = wn * 64 + bp * 16 + ((lane >> 4) << 3) + (lane & 7);
                    const uint32_t off = swz64(rn, ks * 2 + ((lane >> 3) & 1));
                    uint32_t bh[4], bl[4];
                    ldsm4(bh[0], bh[1], bh[2], bh[3], st + ST_BHI + off);
                    ldsm4(bl[0], bl[1], bl[2], bl[3], st + ST_BLO + off);
                    // term-major: 4 independent accumulators between reuse
#pragma unroll
                    for (int mt = 0; mt < 2; mt++)
#pragma unroll
                        for (int h = 0; h < 2; h++)
                            mma16816(acc[mt][2 * bp + h], ah[mt], bh[2 * h], bh[2 * h + 1]);
#pragma unroll
                    for (int mt = 0; mt < 2; mt++)
#pragma unroll
                        for (int h = 0; h < 2; h++)
                            mma16816(acc[mt][2 * bp + h], ah[mt], bl[2 * h], bl[2 * h + 1]);
#pragma unroll
                    for (int mt = 0; mt < 2; mt++)
#pragma unroll
                        for (int h = 0; h < 2; h++)
                            mma16816(acc[mt][2 * bp + h], al[mt], bh[2 * h], bh[2 * h + 1]);
                }
            }
        }

        const int rbase = m0 + wm * 32, cbase = n0 + wn * 64;
        if (Cout) {
#pragma unroll
            for (int mt = 0; mt < 2; mt++) {
#pragma unroll
                for (int nt = 0; nt < 8; nt++) {
                    float* d = acc[mt][nt];
                    const size_t r0 = (size_t)(rbase + mt * 16 + lr) * ldc
                                      + cbase + nt * 8 + lc;
                    *(float2*)(Cout + r0)           = make_float2(d[0], d[1]);
                    *(float2*)(Cout + r0 + 8 * ldc) = make_float2(d[2], d[3]);
                }
            }
        } else {
            const bool do_rope = (freqs != nullptr) && (cbase < rope_cols);
#pragma unroll
            for (int mt = 0; mt < 2; mt++) {
#pragma unroll
                for (int nt = 0; nt < 8; nt++) {
                    float* d = acc[mt][nt];
#pragma unroll
                    for (int half = 0; half < 2; half++) {
                        const int row = rbase + mt * 16 + lr + half * 8;
                        const int col = cbase + nt * 8 + lc;
                        float v0 = d[half * 2], v1 = d[half * 2 + 1];
                        if (do_rope) {
                            const int s = row & (S_LEN - 1);
                            const int p = (col & (HD - 1)) >> 1;
                            float f = __ldg(freqs + s * (HD / 2) + p);
                            float sn, cs;
                            sincosf(f, &sn, &cs);
                            float r0 = v0 * cs - v1 * sn;
                            float r1 = v0 * sn + v1 * cs;
                            v0 = r0; v1 = r1;
                        }
                        __nv_bfloat16 h0 = __float2bfloat16(v0);
                        __nv_bfloat16 h1 = __float2bfloat16(v1);
                        const size_t o = (size_t)row * ldc + col;
                        *(uint32_t*)(Chi + o) = packbf2(h0, h1);
                        *(uint32_t*)(Clo + o) = packbf2(
                            __float2bfloat16(v0 - __bfloat162float(h0)),
                            __float2bfloat16(v1 - __bfloat162float(h1)));
                    }
                }
            }
        }
        __syncthreads();   // epilogue done; smem reuse by next tile safe
    }
}

// ---------------------------------------------------------------------------
// fp32 -> bf16 hi/lo elementwise (for x)
// ---------------------------------------------------------------------------
__global__ void convert_hilo_kernel(const float* __restrict__ in,
                                    __nv_bfloat16* __restrict__ hi,
                                    __nv_bfloat16* __restrict__ lo, int n)
{
    int i = blockIdx.x * blockDim.x + threadIdx.x;
    if (i >= n) return;
    float v = in[i];
    __nv_bfloat16 h = __float2bfloat16(v);
    hi[i] = h;
    lo[i] = __float2bfloat16(v - __bfloat162float(h));
}

// ---------------------------------------------------------------------------
// W [Kd,Nd] fp32 -> Wt hi/lo [Nd,Kd] bf16 (tiled transpose)
// ---------------------------------------------------------------------------
__global__ void transpose_hilo_kernel(const float* __restrict__ W,
                                      __nv_bfloat16* __restrict__ hi,
                                      __nv_bfloat16* __restrict__ lo,
                                      int Kd, int Nd)
{
    __shared__ float t[32][33];
    const int tx = threadIdx.x, ty = threadIdx.y;
    const int k0 = blockIdx.y * 32, n0 = blockIdx.x * 32;
#pragma unroll
    for (int i = 0; i < 4; i++)
        t[ty + i * 8][tx] = W[(size_t)(k0 + ty + i * 8) * Nd + n0 + tx];
    __syncthreads();
#pragma unroll
    for (int i = 0; i < 4; i++) {
        float v = t[tx][ty + i * 8];
        __nv_bfloat16 h = __float2bfloat16(v);
        size_t o = (size_t)(n0 + ty + i * 8) * Kd + k0 + tx;
        hi[o] = h;
        lo[o] = __float2bfloat16(v - __bfloat162float(h));
    }
}

// ---------------------------------------------------------------------------
// HMMA causal flash attention, bf16 hi/lo (3-term QK and PV), fp32 softmax.
// BR=BC=64, 128 threads (4 warps x 16 q-rows). Single-buffered K/V smem
// (104KB => 2 CTAs/SM). Q read from merged qc buffer (stride QC_W); K/V from
// merged KV buffer (stride KV_W, V at +2048). O written at stride D_DIM.
// ---------------------------------------------------------------------------
#define FP   136
#define FPB  272
#define FT   17408
#define SQHI 0
#define SQLO 17408
#define SKHI 34816
#define SKLO 52224
#define SVHI 69632
#define SVLO 87040
#define FL_SMEM 104448

__global__ __launch_bounds__(128)
void flash_hmma_kernel(const __nv_bfloat16* __restrict__ Qhi,
                       const __nv_bfloat16* __restrict__ Qlo,
                       const __nv_bfloat16* __restrict__ KVhi,
                       const __nv_bfloat16* __restrict__ KVlo,
                       __nv_bfloat16* __restrict__ Ohi,
                       __nv_bfloat16* __restrict__ Olo)
{
    extern __shared__ char dsm[];
    const uint32_t sb = smem_u32(dsm);

    const int tid = threadIdx.x, lane = tid & 31, wm = tid >> 5;
    const int lr = lane >> 2, lc2 = (lane & 3) * 2;

    const int bh_ = blockIdx.y;
    const int b = bh_ >> 4, head = bh_ & 15;
    const int qi = gridDim.x - 1 - blockIdx.x;       // heavy blocks first
    const int q0 = qi * 64;
    const size_t baseQ  = ((size_t)b * S_LEN) * QC_W + head * HD;
    const size_t baseKV = ((size_t)b * S_LEN) * KV_W + head * HD;
    const size_t baseO  = ((size_t)b * S_LEN) * D_DIM + head * HD;

#pragma unroll
    for (int j = 0; j < 8; j++) {
        int lin = j * 128 + tid;
        int row = lin >> 4, c16 = lin & 15;
        const size_t so = baseQ + (size_t)(q0 + row) * QC_W + c16 * 8;
        const uint32_t doff = row * FPB + c16 * 16;
        cp16(sb + SQHI + doff, Qhi + so);
        cp16(sb + SQLO + doff, Qlo + so);
    }
    CP_COMMIT();

    float m[2] = {-1e30f, -1e30f}, l[2] = {0.f, 0.f};
    float accO[16][4];
#pragma unroll
    for (int nt = 0; nt < 16; nt++)
#pragma unroll
        for (int e = 0; e < 4; e++) accO[nt][e] = 0.f;

    const float scale = 0.08838834764831845f;
    const int qrow_base = q0 + wm * 16;

    for (int kt = 0; kt <= qi; kt++) {
        const int k0g = kt * 64;
        __syncthreads();
#pragma unroll
        for (int j = 0; j < 8; j++) {
            int lin = j * 128 + tid;
            int row = lin >> 4, c16 = lin & 15;
            const size_t so = baseKV + (size_t)(k0g + row) * KV_W + c16 * 8;
            const uint32_t doff = row * FPB + c16 * 16;
            cp16(sb + SKHI + doff, KVhi + so);
            cp16(sb + SKLO + doff, KVlo + so);
            cp16(sb + SVHI + doff, KVhi + so + 2048);
            cp16(sb + SVLO + doff, KVlo + so + 2048);
        }
        CP_COMMIT();
        asm volatile("cp.async.wait_group 0;" ::: "memory");
        __syncthreads();

        float accS[8][4];
#pragma unroll
        for (int n = 0; n < 8; n++)
#pragma unroll
            for (int e = 0; e < 4; e++) accS[n][e] = 0.f;

#pragma unroll
        for (int ks = 0; ks < 8; ks++) {
            const int kk = ks * 16;
            uint32_t qh[4], ql[4];
            const uint32_t qoff = (wm * 16 + (lane & 15)) * FPB
                                  + (kk + ((lane >> 4) << 3)) * 2;
            ldsm4(qh[0], qh[1], qh[2], qh[3], sb + SQHI + qoff);
            ldsm4(ql[0], ql[1], ql[2], ql[3], sb + SQLO + qoff);
#pragma unroll
            for (int np = 0; np < 4; np++) {
                const uint32_t koff =
                    (np * 16 + (lane & 7) + ((lane >> 4) << 3)) * FPB
                    + (kk + (((lane >> 3) & 1) << 3)) * 2;
                uint32_t bh[4], bl[4];
                ldsm4(bh[0], bh[1], bh[2], bh[3], sb + SKHI + koff);
                ldsm4(bl[0], bl[1], bl[2], bl[3], sb + SKLO + koff);
#pragma unroll
                for (int t = 0; t < 2; t++)
                    mma16816(accS[np * 2 + t], qh, bh[2 * t], bh[2 * t + 1]);
#pragma unroll
                for (int t = 0; t < 2; t++)
                    mma16816(accS[np * 2 + t], qh, bl[2 * t], bl[2 * t + 1]);
#pragma unroll
                for (int t = 0; t < 2; t++)
                    mma16816(accS[np * 2 + t], ql, bh[2 * t], bh[2 * t + 1]);
            }
        }

        const bool diag = (kt == qi);
#pragma unroll
        for (int n = 0; n < 8; n++) {
#pragma unroll
            for (int e = 0; e < 4; e++) {
                float v = accS[n][e] * scale;
                if (diag) {
                    int row = qrow_base + lr + 8 * (e >> 1);
                    int col = k0g + n * 8 + lc2 + (e & 1);
                    if (col > row) v = -1e30f;
                }
                accS[n][e] = v;
            }
        }

#pragma unroll
        for (int h = 0; h < 2; h++) {
            float mt = -1e30f;
#pragma unroll
            for (int n = 0; n < 8; n++)
                mt = fmaxf(mt, fmaxf(accS[n][2 * h], accS[n][2 * h + 1]));
            mt = fmaxf(mt, __shfl_xor_sync(0xffffffffu, mt, 1));
            mt = fmaxf(mt, __shfl_xor_sync(0xffffffffu, mt, 2));
            float mn = fmaxf(m[h], mt);
            float alpha = __expf(m[h] - mn);
            m[h] = mn;
            float lt = 0.f;
#pragma unroll
            for (int n = 0; n < 8; n++) {
                float p0 = __expf(accS[n][2 * h] - mn);
                float p1 = __expf(accS[n][2 * h + 1] - mn);
                accS[n][2 * h] = p0;
                accS[n][2 * h + 1] = p1;
                lt += p0 + p1;
            }
            lt += __shfl_xor_sync(0xffffffffu, lt, 1);
            lt += __shfl_xor_sync(0xffffffffu, lt, 2);
            l[h] = l[h] * alpha + lt;
#pragma unroll
            for (int nt = 0; nt < 16; nt++) {
                accO[nt][2 * h] *= alpha;
                accO[nt][2 * h + 1] *= alpha;
            }
        }

#pragma unroll
        for (int t = 0; t < 4; t++) {
            uint32_t phi[4], plo[4];
#pragma unroll
            for (int half = 0; half < 2; half++) {
                float* s = accS[2 * t + half];
#pragma unroll
                for (int rh = 0; rh < 2; rh++) {
                    float v0 = s[2 * rh], v1 = s[2 * rh + 1];
                    __nv_bfloat16 h0 = __float2bfloat16(v0);
                    __nv_bfloat16 h1 = __float2bfloat16(v1);
                    phi[half * 2 + rh] = packbf2(h0, h1);
                    plo[half * 2 + rh] = packbf2(
                        __float2bfloat16(v0 - __bfloat162float(h0)),
                        __float2bfloat16(v1 - __bfloat162float(h1)));
                }
            }
            const int kk = t * 16;
#pragma unroll
            for (int np = 0; np < 8; np++) {
                const uint32_t voff = (kk + (lane & 15)) * FPB
                                      + (np * 16 + ((lane >> 4) << 3)) * 2;
                uint32_t vh[4], vl[4];
                ldsm4t(vh[0], vh[1], vh[2], vh[3], sb + SVHI + voff);
                ldsm4t(vl[0], vl[1], vl[2], vl[3], sb + SVLO + voff);
#pragma unroll
                for (int u = 0; u < 2; u++)
                    mma16816(accO[np * 2 + u], phi, vh[2 * u], vh[2 * u + 1]);
#pragma unroll
                for (int u = 0; u < 2; u++)
                    mma16816(accO[np * 2 + u], phi, vl[2 * u], vl[2 * u + 1]);
#pragma unroll
                for (int u = 0; u < 2; u++)
                    mma16816(accO[np * 2 + u], plo, vh[2 * u], vh[2 * u + 1]);
            }
        }
    }

    const float inv0 = 1.0f / l[0], inv1 = 1.0f / l[1];
#pragma unroll
    for (int nt = 0; nt < 16; nt++) {
#pragma unroll
        for (int h = 0; h < 2; h++) {
            float inv = h ? inv1 : inv0;
            float v0 = accO[nt][2 * h] * inv;
            float v1 = accO[nt][2 * h + 1] * inv;
            __nv_bfloat16 h0 = __float2bfloat16(v0);
            __nv_bfloat16 h1 = __float2bfloat16(v1);
            const size_t o = baseO
                + (size_t)(qrow_base + lr + 8 * h) * D_DIM + nt * 8 + lc2;
            *(uint32_t*)(Ohi + o) = packbf2(h0, h1);
            *(uint32_t*)(Olo + o) = packbf2(
                __float2bfloat16(v0 - __bfloat162float(h0)),
                __float2bfloat16(v1 - __bfloat162float(h1)));
        }
    }
}

// ---------------------------------------------------------------------------
// Launch
// Inputs: x, freqs, mask(unused: exactly causal), Wq, Wdown, Wkup, Wvup, Wo
// ---------------------------------------------------------------------------
extern "C" void kernel_launch(void* const* d_in, const int* in_sizes, int n_in,
                              void* d_out, int out_size)
{
    const float* x     = (const float*)d_in[0];
    const float* freqs = (const float*)d_in[1];
    const float* Wq    = (const float*)d_in[3];
    const float* Wdn   = (const float*)d_in[4];
    const float* Wku   = (const float*)d_in[5];
    const float* Wvu   = (const float*)d_in[6];
    const float* Wo    = (const float*)d_in[7];
    float* out = (float*)d_out;

    __nv_bfloat16 *xhi, *xlo, *wthi, *wtlo;
    __nv_bfloat16 *qchi, *qclo, *kvhi, *kvlo, *ohi, *olo;
    cudaGetSymbolAddress((void**)&xhi, g_xhi);
    cudaGetSymbolAddress((void**)&xlo, g_xlo);
    cudaGetSymbolAddress((void**)&qchi, g_qchi);
    cudaGetSymbolAddress((void**)&qclo, g_qclo);
    cudaGetSymbolAddress((void**)&kvhi, g_kvhi);
    cudaGetSymbolAddress((void**)&kvlo, g_kvlo);
    cudaGetSymbolAddress((void**)&ohi, g_ohi);
    cudaGetSymbolAddress((void**)&olo, g_olo);
    cudaGetSymbolAddress((void**)&wthi, g_wthi);
    cudaGetSymbolAddress((void**)&wtlo, g_wtlo);

    cudaFuncSetAttribute(gemm_hilo_kernel,
                         cudaFuncAttributeMaxDynamicSharedMemorySize, GK_SMEM_DYN);
    cudaFuncSetAttribute(flash_hmma_kernel,
                         cudaFuncAttributeMaxDynamicSharedMemorySize, FL_SMEM);

    dim3 tb(32, 8);
    const int nx = ROWS_TOT * D_DIM;

    // Prep: transposes + x convert (bandwidth-bound)
    transpose_hilo_kernel<<<dim3(64, 64), tb>>>(Wq,  wthi + OFF_WQ,  wtlo + OFF_WQ,  2048, 2048);
    transpose_hilo_kernel<<<dim3(16, 64), tb>>>(Wdn, wthi + OFF_WDN, wtlo + OFF_WDN, 2048, 512);
    convert_hilo_kernel<<<nx / 256, 256>>>(x, xhi, xlo, nx);
    transpose_hilo_kernel<<<dim3(64, 16), tb>>>(Wku, wthi + OFF_WKU, wtlo + OFF_WKU, 512, 2048);

    // Merged Q|c projection: x @ [Wq|Wdown], N=2560, RoPE on cols < 2048.
    // 640 tiles, persistent grid (kills tail underfill of separate launches).
    gemm_hilo_kernel<<<GK_GRID, 256, GK_SMEM_DYN>>>(
        xhi, xlo, wthi + OFF_WQ, wtlo + OFF_WQ,
        nullptr, qchi, qclo, freqs, 2048,
        ROWS_TOT, QC_W, D_DIM, D_DIM, QC_W);

    transpose_hilo_kernel<<<dim3(64, 16), tb>>>(Wvu, wthi + OFF_WVU, wtlo + OFF_WVU, 512, 2048);
    transpose_hilo_kernel<<<dim3(64, 64), tb>>>(Wo,  wthi + OFF_WO,  wtlo + OFF_WO,  2048, 2048);

    // Merged K|V up-projection: c @ [Wkup|Wvup], N=4096, RoPE on cols < 2048.
    // A = columns [2048,2560) of qc (lda = QC_W).
    gemm_hilo_kernel<<<GK_GRID, 256, GK_SMEM_DYN>>>(
        qchi + 2048, qclo + 2048, wthi + OFF_WKU, wtlo + OFF_WKU,
        nullptr, kvhi, kvlo, freqs, 2048,
        ROWS_TOT, KV_W, LAT, QC_W, KV_W);

    // Flash attention (causal, HMMA hi/lo) -> O as bf16 hi/lo
    flash_hmma_kernel<<<dim3(S_LEN / 64, BATCH * NH), 128, FL_SMEM>>>(
        qchi, qclo, kvhi, kvlo, ohi, olo);

    // Output projection (fp32 out)
    gemm_hilo_kernel<<<GK_GRID, 256, GK_SMEM_DYN>>>(
        ohi, olo, wthi + OFF_WO, wtlo + OFF_WO,
        out, nullptr, nullptr, nullptr, 0,
        ROWS_TOT, D_DIM, D_DIM, D_DIM, D_DIM);
}

// round 12
// speedup vs baseline: 1.2786x; 1.0073x over previous
#include <cuda_runtime.h>
#include <cuda_bf16.h>
#include <cstdint>
#include <math.h>

// Problem constants
#define BATCH   2
#define S_LEN   2048
#define D_DIM   2048
#define NH      16
#define HD      128
#define LAT     512
#define ROWS_TOT (BATCH * S_LEN)   // 4096
#define KV_W    4096               // merged K|V row width
#define QC_W    2560               // merged Q|c row width (2048 Q + 512 c)

// ---------------------------------------------------------------------------
// Scratch (__device__ globals; allocation-free rule)
// ---------------------------------------------------------------------------
__device__ __nv_bfloat16 g_xhi[ROWS_TOT * D_DIM];
__device__ __nv_bfloat16 g_xlo[ROWS_TOT * D_DIM];
__device__ __nv_bfloat16 g_qchi[ROWS_TOT * QC_W];   // [0,2048)=Q(roped), [2048,2560)=c
__device__ __nv_bfloat16 g_qclo[ROWS_TOT * QC_W];
__device__ __nv_bfloat16 g_kvhi[ROWS_TOT * KV_W];   // [0,2048)=K(roped), [2048,4096)=V
__device__ __nv_bfloat16 g_kvlo[ROWS_TOT * KV_W];
__device__ __nv_bfloat16 g_ohi[ROWS_TOT * D_DIM];
__device__ __nv_bfloat16 g_olo[ROWS_TOT * D_DIM];
__device__ float2 g_cs[S_LEN * (HD / 2)];           // RoPE cos/sin table

// Transposed-weight pool ([N,K] K-major bf16), hi and lo parts.
#define OFF_WQ  0
#define OFF_WDN 4194304
#define OFF_WKU 5242880
#define OFF_WVU 6291456
#define OFF_WO  7340032
#define WT_TOTAL 11534336
__device__ __nv_bfloat16 g_wthi[WT_TOTAL];
__device__ __nv_bfloat16 g_wtlo[WT_TOTAL];

// ---------------------------------------------------------------------------
// PTX helpers (sm_80+ features only — harness targets plain sm_103)
// ---------------------------------------------------------------------------
__device__ __forceinline__ uint32_t smem_u32(const void* p) {
    uint32_t a;
    asm("{ .reg .u64 t; cvta.to.shared.u64 t, %1; cvt.u32.u64 %0, t; }"
        : "=r"(a) : "l"(p));
    return a;
}
__device__ __forceinline__ void cp16(uint32_t dst, const void* src) {
    asm volatile("cp.async.cg.shared.global [%0], [%1], 16;" :: "r"(dst), "l"(src));
}
#define CP_COMMIT() asm volatile("cp.async.commit_group;" ::: "memory")

__device__ __forceinline__ void ldsm4(uint32_t& r0, uint32_t& r1,
                                      uint32_t& r2, uint32_t& r3, uint32_t a) {
    asm volatile("ldmatrix.sync.aligned.m8n8.x4.shared.b16 {%0,%1,%2,%3}, [%4];"
                 : "=r"(r0), "=r"(r1), "=r"(r2), "=r"(r3) : "r"(a));
}
__device__ __forceinline__ void ldsm4t(uint32_t& r0, uint32_t& r1,
                                       uint32_t& r2, uint32_t& r3, uint32_t a) {
    asm volatile("ldmatrix.sync.aligned.m8n8.x4.trans.shared.b16 {%0,%1,%2,%3}, [%4];"
                 : "=r"(r0), "=r"(r1), "=r"(r2), "=r"(r3) : "r"(a));
}
// Non-volatile: pure register op; lets ptxas interleave MMAs to break
// accumulator RAW chains.
__device__ __forceinline__ void mma16816(float* d, const uint32_t* a,
                                         uint32_t b0, uint32_t b1) {
    asm("mma.sync.aligned.m16n8k16.row.col.f32.bf16.bf16.f32 "
        "{%0,%1,%2,%3}, {%4,%5,%6,%7}, {%8,%9}, {%0,%1,%2,%3};"
        : "+f"(d[0]), "+f"(d[1]), "+f"(d[2]), "+f"(d[3])
        : "r"(a[0]), "r"(a[1]), "r"(a[2]), "r"(a[3]), "r"(b0), "r"(b1));
}
__device__ __forceinline__ uint32_t packbf2(__nv_bfloat16 x, __nv_bfloat16 y) {
    __nv_bfloat162 t(x, y);
    return *(uint32_t*)&t;
}

// XOR chunk swizzle for 64B-pitch rows (4 x 16B chunks per row).
__device__ __forceinline__ uint32_t swz64(int row, int chunk) {
    return (uint32_t)(row * 64 + ((chunk ^ ((row >> 1) & 3)) << 4));
}

// ---------------------------------------------------------------------------
// HMMA bf16 hi/lo GEMM (persistent). Same mainloop as round 11 (known-good).
// RoPE epilogue now reads the precomputed cos/sin table (no sincosf).
// ---------------------------------------------------------------------------
#define ST_AHI  0
#define ST_ALO  8192
#define ST_BHI  16384
#define ST_BLO  24576
#define STAGE_B 32768
#define GK_SMEM_DYN (3 * STAGE_B)   // 96 KB
#define GK_GRID 296                 // 2 CTAs x 148 SMs

__global__ __launch_bounds__(256, 2)
void gemm_hilo_kernel(const __nv_bfloat16* __restrict__ Ahi,
                      const __nv_bfloat16* __restrict__ Alo,
                      const __nv_bfloat16* __restrict__ Bhi,
                      const __nv_bfloat16* __restrict__ Blo,
                      float* __restrict__ Cout,
                      __nv_bfloat16* __restrict__ Chi,
                      __nv_bfloat16* __restrict__ Clo,
                      const float2* __restrict__ cstab,
                      int rope_cols,
                      int M, int N, int K, int lda, int ldc)
{
    extern __shared__ char dsm[];
    const uint32_t sbase = smem_u32(dsm);
    const int tid = threadIdx.x, lane = tid & 31, wid = tid >> 5;
    const int wm = wid & 3, wn = wid >> 2;           // 4 x 2 warp grid
    const int lrow = tid >> 1;
    const int lc0  = (tid & 1) * 2;
    const int lr = lane >> 2, lc = (lane & 3) * 2;
    const int nk = K >> 5;
    const int ntx = N >> 7;
    const int ntiles = (M >> 7) * ntx;

    for (int tile = blockIdx.x; tile < ntiles; tile += gridDim.x) {
        const int tyi = tile / ntx;
        const int txi = tile - tyi * ntx;
        const int m0 = tyi * 128, n0 = txi * 128;

        const __nv_bfloat16* gAh = Ahi + (size_t)m0 * lda;
        const __nv_bfloat16* gAl = Alo + (size_t)m0 * lda;
        const __nv_bfloat16* gBh = Bhi + (size_t)n0 * K;
        const __nv_bfloat16* gBl = Blo + (size_t)n0 * K;

        float acc[2][8][4];
#pragma unroll
        for (int mt = 0; mt < 2; mt++)
#pragma unroll
            for (int nt = 0; nt < 8; nt++)
#pragma unroll
                for (int r = 0; r < 4; r++) acc[mt][nt][r] = 0.f;

        auto load_stage = [&](int buf, int kc) {
            const uint32_t st = sbase + buf * STAGE_B;
            const size_t koff = (size_t)kc * 32;
#pragma unroll
            for (int t = 0; t < 2; t++) {
                const int c = lc0 + t;
                const uint32_t doff = swz64(lrow, c);
                cp16(st + ST_AHI + doff, gAh + (size_t)lrow * lda + koff + c * 8);
                cp16(st + ST_ALO + doff, gAl + (size_t)lrow * lda + koff + c * 8);
                cp16(st + ST_BHI + doff, gBh + (size_t)lrow * K + koff + c * 8);
                cp16(st + ST_BLO + doff, gBl + (size_t)lrow * K + koff + c * 8);
            }
            CP_COMMIT();
        };

        load_stage(0, 0);
        if (nk > 1) load_stage(1, 1);

        for (int k = 0; k < nk; k++) {
            if (k + 1 < nk)
                asm volatile("cp.async.wait_group 1;" ::: "memory");
            else
                asm volatile("cp.async.wait_group 0;" ::: "memory");
            __syncthreads();

            if (k + 2 < nk) load_stage((k + 2) % 3, k + 2);

            const uint32_t st = sbase + (k % 3) * STAGE_B;
#pragma unroll
            for (int ks = 0; ks < 2; ks++) {
                uint32_t ah[2][4], al[2][4];
#pragma unroll
                for (int mt = 0; mt < 2; mt++) {
                    const int row = wm * 32 + mt * 16 + (lane & 15);
                    const uint32_t off = swz64(row, ks * 2 + (lane >> 4));
                    ldsm4(ah[mt][0], ah[mt][1], ah[mt][2], ah[mt][3],
                          st + ST_AHI + off);
                    ldsm4(al[mt][0], al[mt][1], al[mt][2], al[mt][3],
                          st + ST_ALO + off);
                }
#pragma unroll
                for (int bp = 0; bp < 4; bp++) {
                    const int rn = wn * 64 + bp * 16 + ((lane >> 4) << 3) + (lane & 7);
                    const uint32_t off = swz64(rn, ks * 2 + ((lane >> 3) & 1));
                    uint32_t bh[4], bl[4];
                    ldsm4(bh[0], bh[1], bh[2], bh[3], st + ST_BHI + off);
                    ldsm4(bl[0], bl[1], bl[2], bl[3], st + ST_BLO + off);
#pragma unroll
                    for (int mt = 0; mt < 2; mt++)
#pragma unroll
                        for (int h = 0; h < 2; h++)
                            mma16816(acc[mt][2 * bp + h], ah[mt], bh[2 * h], bh[2 * h + 1]);
#pragma unroll
                    for (int mt = 0; mt < 2; mt++)
#pragma unroll
                        for (int h = 0; h < 2; h++)
                            mma16816(acc[mt][2 * bp + h], ah[mt], bl[2 * h], bl[2 * h + 1]);
#pragma unroll
                    for (int mt = 0; mt < 2; mt++)
#pragma unroll
                        for (int h = 0; h < 2; h++)
                            mma16816(acc[mt][2 * bp + h], al[mt], bh[2 * h], bh[2 * h + 1]);
                }
            }
        }

        const int rbase = m0 + wm * 32, cbase = n0 + wn * 64;
        if (Cout) {
#pragma unroll
            for (int mt = 0; mt < 2; mt++) {
#pragma unroll
                for (int nt = 0; nt < 8; nt++) {
                    float* d = acc[mt][nt];
                    const size_t r0 = (size_t)(rbase + mt * 16 + lr) * ldc
                                      + cbase + nt * 8 + lc;
                    *(float2*)(Cout + r0)           = make_float2(d[0], d[1]);
                    *(float2*)(Cout + r0 + 8 * ldc) = make_float2(d[2], d[3]);
                }
            }
        } else {
            const bool do_rope = (cstab != nullptr) && (cbase < rope_cols);
#pragma unroll
            for (int mt = 0; mt < 2; mt++) {
#pragma unroll
                for (int nt = 0; nt < 8; nt++) {
                    float* d = acc[mt][nt];
#pragma unroll
                    for (int half = 0; half < 2; half++) {
                        const int row = rbase + mt * 16 + lr + half * 8;
                        const int col = cbase + nt * 8 + lc;
                        float v0 = d[half * 2], v1 = d[half * 2 + 1];
                        if (do_rope) {
                            const int s = row & (S_LEN - 1);
                            const int p = (col & (HD - 1)) >> 1;
                            float2 cs = __ldg(cstab + s * (HD / 2) + p);
                            float r0 = v0 * cs.x - v1 * cs.y;
                            float r1 = v0 * cs.y + v1 * cs.x;
                            v0 = r0; v1 = r1;
                        }
                        __nv_bfloat16 h0 = __float2bfloat16(v0);
                        __nv_bfloat16 h1 = __float2bfloat16(v1);
                        const size_t o = (size_t)row * ldc + col;
                        *(uint32_t*)(Chi + o) = packbf2(h0, h1);
                        *(uint32_t*)(Clo + o) = packbf2(
                            __float2bfloat16(v0 - __bfloat162float(h0)),
                            __float2bfloat16(v1 - __bfloat162float(h1)));
                    }
                }
            }
        }
        __syncthreads();
    }
}

// ---------------------------------------------------------------------------
// Prep kernels
// ---------------------------------------------------------------------------
__global__ void convert_hilo_kernel(const float* __restrict__ in,
                                    __nv_bfloat16* __restrict__ hi,
                                    __nv_bfloat16* __restrict__ lo, int n)
{
    int i = blockIdx.x * blockDim.x + threadIdx.x;
    if (i >= n) return;
    float v = in[i];
    __nv_bfloat16 h = __float2bfloat16(v);
    hi[i] = h;
    lo[i] = __float2bfloat16(v - __bfloat162float(h));
}

__global__ void rope_table_kernel(const float* __restrict__ freqs,
                                  float2* __restrict__ cstab)
{
    int i = blockIdx.x * blockDim.x + threadIdx.x;
    if (i >= S_LEN * (HD / 2)) return;
    float f = freqs[i];
    float sn, cs;
    sincosf(f, &sn, &cs);
    cstab[i] = make_float2(cs, sn);
}

__global__ void transpose_hilo_kernel(const float* __restrict__ W,
                                      __nv_bfloat16* __restrict__ hi,
                                      __nv_bfloat16* __restrict__ lo,
                                      int Kd, int Nd)
{
    __shared__ float t[32][33];
    const int tx = threadIdx.x, ty = threadIdx.y;
    const int k0 = blockIdx.y * 32, n0 = blockIdx.x * 32;
#pragma unroll
    for (int i = 0; i < 4; i++)
        t[ty + i * 8][tx] = W[(size_t)(k0 + ty + i * 8) * Nd + n0 + tx];
    __syncthreads();
#pragma unroll
    for (int i = 0; i < 4; i++) {
        float v = t[tx][ty + i * 8];
        __nv_bfloat16 h = __float2bfloat16(v);
        size_t o = (size_t)(n0 + ty + i * 8) * Kd + k0 + tx;
        hi[o] = h;
        lo[o] = __float2bfloat16(v - __bfloat162float(h));
    }
}

// ---------------------------------------------------------------------------
// HMMA causal flash attention, bf16 hi/lo, fp32 softmax.
// BR=BC=64, 128 threads. NEW: staggered K/V cp.async groups —
//   wait K only before QK^T (V lands under S-compute),
//   prefetch next K during softmax+PV, prefetch next V after PV.
// ---------------------------------------------------------------------------
#define FP   136
#define FPB  272
#define SQHI 0
#define SQLO 17408
#define SKHI 34816
#define SKLO 52224
#define SVHI 69632
#define SVLO 87040
#define FL_SMEM 104448

__global__ __launch_bounds__(128)
void flash_hmma_kernel(const __nv_bfloat16* __restrict__ Qhi,
                       const __nv_bfloat16* __restrict__ Qlo,
                       const __nv_bfloat16* __restrict__ KVhi,
                       const __nv_bfloat16* __restrict__ KVlo,
                       __nv_bfloat16* __restrict__ Ohi,
                       __nv_bfloat16* __restrict__ Olo)
{
    extern __shared__ char dsm[];
    const uint32_t sb = smem_u32(dsm);

    const int tid = threadIdx.x, lane = tid & 31, wm = tid >> 5;
    const int lr = lane >> 2, lc2 = (lane & 3) * 2;

    const int bh_ = blockIdx.y;
    const int b = bh_ >> 4, head = bh_ & 15;
    const int qi = gridDim.x - 1 - blockIdx.x;       // heavy blocks first
    const int q0 = qi * 64;
    const size_t baseQ  = ((size_t)b * S_LEN) * QC_W + head * HD;
    const size_t baseKV = ((size_t)b * S_LEN) * KV_W + head * HD;
    const size_t baseO  = ((size_t)b * S_LEN) * D_DIM + head * HD;

    auto load_k = [&](int k0g) {
#pragma unroll
        for (int j = 0; j < 8; j++) {
            int lin = j * 128 + tid;
            int row = lin >> 4, c16 = lin & 15;
            const size_t so = baseKV + (size_t)(k0g + row) * KV_W + c16 * 8;
            const uint32_t doff = row * FPB + c16 * 16;
            cp16(sb + SKHI + doff, KVhi + so);
            cp16(sb + SKLO + doff, KVlo + so);
        }
        CP_COMMIT();
    };
    auto load_v = [&](int k0g) {
#pragma unroll
        for (int j = 0; j < 8; j++) {
            int lin = j * 128 + tid;
            int row = lin >> 4, c16 = lin & 15;
            const size_t so = baseKV + (size_t)(k0g + row) * KV_W + c16 * 8 + 2048;
            const uint32_t doff = row * FPB + c16 * 16;
            cp16(sb + SVHI + doff, KVhi + so);
            cp16(sb + SVLO + doff, KVlo + so);
        }
        CP_COMMIT();
    };

    // Prologue: Q, K0, V0 in flight (3 commit groups).
#pragma unroll
    for (int j = 0; j < 8; j++) {
        int lin = j * 128 + tid;
        int row = lin >> 4, c16 = lin & 15;
        const size_t so = baseQ + (size_t)(q0 + row) * QC_W + c16 * 8;
        const uint32_t doff = row * FPB + c16 * 16;
        cp16(sb + SQHI + doff, Qhi + so);
        cp16(sb + SQLO + doff, Qlo + so);
    }
    CP_COMMIT();
    load_k(0);
    load_v(0);

    float m[2] = {-1e30f, -1e30f}, l[2] = {0.f, 0.f};
    float accO[16][4];
#pragma unroll
    for (int nt = 0; nt < 16; nt++)
#pragma unroll
        for (int e = 0; e < 4; e++) accO[nt][e] = 0.f;

    const float scale = 0.08838834764831845f;
    const int qrow_base = q0 + wm * 16;

    for (int kt = 0; kt <= qi; kt++) {
        const int k0g = kt * 64;
        const bool more = (kt < qi);

        // K_kt (and Q) complete; V_kt may still be in flight.
        asm volatile("cp.async.wait_group 1;" ::: "memory");
        __syncthreads();

        // ---- S = Q K^T ----
        float accS[8][4];
#pragma unroll
        for (int n = 0; n < 8; n++)
#pragma unroll
            for (int e = 0; e < 4; e++) accS[n][e] = 0.f;

#pragma unroll
        for (int ks = 0; ks < 8; ks++) {
            const int kk = ks * 16;
            uint32_t qh[4], ql[4];
            const uint32_t qoff = (wm * 16 + (lane & 15)) * FPB
                                  + (kk + ((lane >> 4) << 3)) * 2;
            ldsm4(qh[0], qh[1], qh[2], qh[3], sb + SQHI + qoff);
            ldsm4(ql[0], ql[1], ql[2], ql[3], sb + SQLO + qoff);
#pragma unroll
            for (int np = 0; np < 4; np++) {
                const uint32_t koff =
                    (np * 16 + (lane & 7) + ((lane >> 4) << 3)) * FPB
                    + (kk + (((lane >> 3) & 1) << 3)) * 2;
                uint32_t bh[4], bl[4];
                ldsm4(bh[0], bh[1], bh[2], bh[3], sb + SKHI + koff);
                ldsm4(bl[0], bl[1], bl[2], bl[3], sb + SKLO + koff);
#pragma unroll
                for (int t = 0; t < 2; t++)
                    mma16816(accS[np * 2 + t], qh, bh[2 * t], bh[2 * t + 1]);
#pragma unroll
                for (int t = 0; t < 2; t++)
                    mma16816(accS[np * 2 + t], qh, bl[2 * t], bl[2 * t + 1]);
#pragma unroll
                for (int t = 0; t < 2; t++)
                    mma16816(accS[np * 2 + t], ql, bh[2 * t], bh[2 * t + 1]);
            }
        }

        // All warps done reading the K tile; safe to overwrite with next K.
        __syncthreads();
        if (more) {
            load_k(k0g + 64);
            // V_kt done (only K_{kt+1} may remain pending).
            asm volatile("cp.async.wait_group 1;" ::: "memory");
        } else {
            asm volatile("cp.async.wait_group 0;" ::: "memory");
        }
        __syncthreads();

        // ---- mask + online softmax ----
        const bool diag = (kt == qi);
#pragma unroll
        for (int n = 0; n < 8; n++) {
#pragma unroll
            for (int e = 0; e < 4; e++) {
                float v = accS[n][e] * scale;
                if (diag) {
                    int row = qrow_base + lr + 8 * (e >> 1);
                    int col = k0g + n * 8 + lc2 + (e & 1);
                    if (col > row) v = -1e30f;
                }
                accS[n][e] = v;
            }
        }

#pragma unroll
        for (int h = 0; h < 2; h++) {
            float mt = -1e30f;
#pragma unroll
            for (int n = 0; n < 8; n++)
                mt = fmaxf(mt, fmaxf(accS[n][2 * h], accS[n][2 * h + 1]));
            mt = fmaxf(mt, __shfl_xor_sync(0xffffffffu, mt, 1));
            mt = fmaxf(mt, __shfl_xor_sync(0xffffffffu, mt, 2));
            float mn = fmaxf(m[h], mt);
            float alpha = __expf(m[h] - mn);
            m[h] = mn;
            float lt = 0.f;
#pragma unroll
            for (int n = 0; n < 8; n++) {
                float p0 = __expf(accS[n][2 * h] - mn);
                float p1 = __expf(accS[n][2 * h + 1] - mn);
                accS[n][2 * h] = p0;
                accS[n][2 * h + 1] = p1;
                lt += p0 + p1;
            }
            lt += __shfl_xor_sync(0xffffffffu, lt, 1);
            lt += __shfl_xor_sync(0xffffffffu, lt, 2);
            l[h] = l[h] * alpha + lt;
#pragma unroll
            for (int nt = 0; nt < 16; nt++) {
                accO[nt][2 * h] *= alpha;
                accO[nt][2 * h + 1] *= alpha;
            }
        }

        // ---- O += P V ----
#pragma unroll
        for (int t = 0; t < 4; t++) {
            uint32_t phi[4], plo[4];
#pragma unroll
            for (int half = 0; half < 2; half++) {
                float* s = accS[2 * t + half];
#pragma unroll
                for (int rh = 0; rh < 2; rh++) {
                    float v0 = s[2 * rh], v1 = s[2 * rh + 1];
                    __nv_bfloat16 h0 = __float2bfloat16(v0);
                    __nv_bfloat16 h1 = __float2bfloat16(v1);
                    phi[half * 2 + rh] = packbf2(h0, h1);
                    plo[half * 2 + rh] = packbf2(
                        __float2bfloat16(v0 - __bfloat162float(h0)),
                        __float2bfloat16(v1 - __bfloat162float(h1)));
                }
            }
            const int kk = t * 16;
#pragma unroll
            for (int np = 0; np < 8; np++) {
                const uint32_t voff = (kk + (lane & 15)) * FPB
                                      + (np * 16 + ((lane >> 4) << 3)) * 2;
                uint32_t vh[4], vl[4];
                ldsm4t(vh[0], vh[1], vh[2], vh[3], sb + SVHI + voff);
                ldsm4t(vl[0], vl[1], vl[2], vl[3], sb + SVLO + voff);
#pragma unroll
                for (int u = 0; u < 2; u++)
                    mma16816(accO[np * 2 + u], phi, vh[2 * u], vh[2 * u + 1]);
#pragma unroll
                for (int u = 0; u < 2; u++)
                    mma16816(accO[np * 2 + u], phi, vl[2 * u], vl[2 * u + 1]);
#pragma unroll
                for (int u = 0; u < 2; u++)
                    mma16816(accO[np * 2 + u], plo, vh[2 * u], vh[2 * u + 1]);
            }
        }

        // All warps done reading the V tile; prefetch next V.
        if (more) {
            __syncthreads();
            load_v(k0g + 64);
        }
    }

    const float inv0 = 1.0f / l[0], inv1 = 1.0f / l[1];
#pragma unroll
    for (int nt = 0; nt < 16; nt++) {
#pragma unroll
        for (int h = 0; h < 2; h++) {
            float inv = h ? inv1 : inv0;
            float v0 = accO[nt][2 * h] * inv;
            float v1 = accO[nt][2 * h + 1] * inv;
            __nv_bfloat16 h0 = __float2bfloat16(v0);
            __nv_bfloat16 h1 = __float2bfloat16(v1);
            const size_t o = baseO
                + (size_t)(qrow_base + lr + 8 * h) * D_DIM + nt * 8 + lc2;
            *(uint32_t*)(Ohi + o) = packbf2(h0, h1);
            *(uint32_t*)(Olo + o) = packbf2(
                __float2bfloat16(v0 - __bfloat162float(h0)),
                __float2bfloat16(v1 - __bfloat162float(h1)));
        }
    }
}

// ---------------------------------------------------------------------------
// Launch
// Inputs: x, freqs, mask(unused: exactly causal), Wq, Wdown, Wkup, Wvup, Wo
// ---------------------------------------------------------------------------
extern "C" void kernel_launch(void* const* d_in, const int* in_sizes, int n_in,
                              void* d_out, int out_size)
{
    const float* x     = (const float*)d_in[0];
    const float* freqs = (const float*)d_in[1];
    const float* Wq    = (const float*)d_in[3];
    const float* Wdn   = (const float*)d_in[4];
    const float* Wku   = (const float*)d_in[5];
    const float* Wvu   = (const float*)d_in[6];
    const float* Wo    = (const float*)d_in[7];
    float* out = (float*)d_out;

    __nv_bfloat16 *xhi, *xlo, *wthi, *wtlo;
    __nv_bfloat16 *qchi, *qclo, *kvhi, *kvlo, *ohi, *olo;
    float2* cstab;
    cudaGetSymbolAddress((void**)&xhi, g_xhi);
    cudaGetSymbolAddress((void**)&xlo, g_xlo);
    cudaGetSymbolAddress((void**)&qchi, g_qchi);
    cudaGetSymbolAddress((void**)&qclo, g_qclo);
    cudaGetSymbolAddress((void**)&kvhi, g_kvhi);
    cudaGetSymbolAddress((void**)&kvlo, g_kvlo);
    cudaGetSymbolAddress((void**)&ohi, g_ohi);
    cudaGetSymbolAddress((void**)&olo, g_olo);
    cudaGetSymbolAddress((void**)&wthi, g_wthi);
    cudaGetSymbolAddress((void**)&wtlo, g_wtlo);
    cudaGetSymbolAddress((void**)&cstab, g_cs);

    cudaFuncSetAttribute(gemm_hilo_kernel,
                         cudaFuncAttributeMaxDynamicSharedMemorySize, GK_SMEM_DYN);
    cudaFuncSetAttribute(flash_hmma_kernel,
                         cudaFuncAttributeMaxDynamicSharedMemorySize, FL_SMEM);

    dim3 tb(32, 8);
    const int nx = ROWS_TOT * D_DIM;
    const int ncs = S_LEN * (HD / 2);

    // Prep (bandwidth-bound)
    transpose_hilo_kernel<<<dim3(64, 64), tb>>>(Wq,  wthi + OFF_WQ,  wtlo + OFF_WQ,  2048, 2048);
    transpose_hilo_kernel<<<dim3(16, 64), tb>>>(Wdn, wthi + OFF_WDN, wtlo + OFF_WDN, 2048, 512);
    convert_hilo_kernel<<<nx / 256, 256>>>(x, xhi, xlo, nx);
    rope_table_kernel<<<(ncs + 255) / 256, 256>>>(freqs, cstab);
    transpose_hilo_kernel<<<dim3(64, 16), tb>>>(Wku, wthi + OFF_WKU, wtlo + OFF_WKU, 512, 2048);

    // Merged Q|c projection: x @ [Wq|Wdown], N=2560, RoPE on cols < 2048.
    gemm_hilo_kernel<<<GK_GRID, 256, GK_SMEM_DYN>>>(
        xhi, xlo, wthi + OFF_WQ, wtlo + OFF_WQ,
        nullptr, qchi, qclo, cstab, 2048,
        ROWS_TOT, QC_W, D_DIM, D_DIM, QC_W);

    transpose_hilo_kernel<<<dim3(64, 16), tb>>>(Wvu, wthi + OFF_WVU, wtlo + OFF_WVU, 512, 2048);
    transpose_hilo_kernel<<<dim3(64, 64), tb>>>(Wo,  wthi + OFF_WO,  wtlo + OFF_WO,  2048, 2048);

    // Merged K|V up-projection: c @ [Wkup|Wvup], N=4096, RoPE on cols < 2048.
    gemm_hilo_kernel<<<GK_GRID, 256, GK_SMEM_DYN>>>(
        qchi + 2048, qclo + 2048, wthi + OFF_WKU, wtlo + OFF_WKU,
        nullptr, kvhi, kvlo, cstab, 2048,
        ROWS_TOT, KV_W, LAT, QC_W, KV_W);

    // Flash attention (causal, HMMA hi/lo, staggered K/V pipeline)
    flash_hmma_kernel<<<dim3(S_LEN / 64, BATCH * NH), 128, FL_SMEM>>>(
        qchi, qclo, kvhi, kvlo, ohi, olo);

    // Output projection (fp32 out)
    gemm_hilo_kernel<<<GK_GRID, 256, GK_SMEM_DYN>>>(
        ohi, olo, wthi + OFF_WO, wtlo + OFF_WO,
        out, nullptr, nullptr, nullptr, 0,
        ROWS_TOT, D_DIM, D_DIM, D_DIM, D_DIM);
}